// round 10
// baseline (speedup 1.0000x reference)
#include <cuda_runtime.h>
#include <cuda_fp16.h>
#include <math.h>
#include <stdint.h>

#define B_    2
#define S_    4096
#define HID_  2048
#define NH_   32
#define NKV_  8
#define HD_   64
#define ROWS_ (B_ * S_)          /* 8192 */
#define KVW_  (NKV_ * HD_)       /* 512  */

#define CTX_SCALE   (1.0f / 1024.0f)
#define CTX_UNSCALE 1024.0f

// weight offsets in the combined transposed-weight buffer (elements)
#define WQOFF 0
#define WKOFF (2048 * 2048)
#define WVOFF (WKOFF + 512 * 2048)
#define WPOFF (WVOFF + 512 * 2048)
#define WOOFF (WPOFF + 2048 * 2048)
#define WTOT  (WOOFF + 2048 * 2048)   /* 7168 * 2048 */

// ---------------- device scratch (no allocs allowed) ----------------
__device__ float g_q  [(size_t)ROWS_ * HID_];
__device__ float g_k  [(size_t)ROWS_ * KVW_];
__device__ float g_v  [(size_t)ROWS_ * KVW_];
__device__ float g_phi[(size_t)ROWS_ * HID_];
__device__ float g_qg [B_ * HID_];
__device__ float g_log[B_ * NH_ * S_];
__device__ float g_out[B_ * NH_ * HD_ * HD_];

__device__ __half g_xhi [(size_t)ROWS_ * HID_];
__device__ __half g_xlo [(size_t)ROWS_ * HID_];
__device__ __half g_whi [(size_t)WTOT];
__device__ __half g_wklo[(size_t)KVW_ * HID_];   // lo part for Wk only
__device__ __half g_phihi[(size_t)ROWS_ * HID_];
__device__ __half g_philo[(size_t)ROWS_ * HID_];

// ================= split-fp16 tensor-core GEMM (ldmatrix fragments) =================
// 2-pass: C = (Ahi+Alo) @ Bhi^T * outScale      (exact A, fp16-quantized B)
// 3-pass: C = (Ahi+Alo) @ (Bhi+Blo)^T           (exact A, ~fp32 B; for Wk)
// Block 128x128, BK=32, 8 warps (warp tile 32x64), cp.async double buffer.

#define GPAD 40                 // smem row stride in fp16 elems (conflict-free)
#define SEC  (128 * GPAD)       // 5120 elems per component tile
#define STAGE2 (3 * SEC)        // Ahi, Alo, Bhi
#define SMEM2  (2 * STAGE2 * 2) /* 61440 */
#define STAGE3 (4 * SEC)        // Ahi, Alo, Bhi, Blo
#define SMEM3  (2 * STAGE3 * 2) /* 81920 */

__device__ __forceinline__ void cpasync16(unsigned smaddr, const void* g) {
    asm volatile("cp.async.cg.shared.global [%0], [%1], 16;" :: "r"(smaddr), "l"(g));
}

__device__ __forceinline__ unsigned smaddr_of(const void* p) {
    return (unsigned)__cvta_generic_to_shared(p);
}

#define MMA_FP16(c, a, b0, b1)                                              \
    asm volatile("mma.sync.aligned.m16n8k16.row.col.f32.f16.f16.f32 "       \
                 "{%0,%1,%2,%3}, {%4,%5,%6,%7}, {%8,%9}, {%0,%1,%2,%3};"    \
                 : "+f"(c[0]), "+f"(c[1]), "+f"(c[2]), "+f"(c[3])           \
                 : "r"(a[0]), "r"(a[1]), "r"(a[2]), "r"(a[3]),              \
                   "r"(b0), "r"(b1))

#define LDSM_X4(r0, r1, r2, r3, addr)                                       \
    asm volatile("ldmatrix.sync.aligned.m8n8.x4.shared.b16 {%0,%1,%2,%3}, [%4];" \
                 : "=r"(r0), "=r"(r1), "=r"(r2), "=r"(r3) : "r"(addr))

__device__ __forceinline__ void stage_load2(
    const __half* Ahi, const __half* Alo, const __half* Bhi,
    __half* sm, int tid, int K, int t)
{
#pragma unroll
    for (int i = 0; i < 2; i++) {
        const int idx = tid + i * 256;
        const int r   = idx >> 2;
        const int c8  = (idx & 3) * 8;
        const size_t goff = (size_t)r * K + (size_t)t * 32 + c8;
        const int soff = r * GPAD + c8;
        cpasync16(smaddr_of(sm + soff),           Ahi + goff);
        cpasync16(smaddr_of(sm + SEC + soff),     Alo + goff);
        cpasync16(smaddr_of(sm + 2 * SEC + soff), Bhi + goff);
    }
}

__global__ __launch_bounds__(256)
void fp16split_gemm(const __half* __restrict__ Ahi, const __half* __restrict__ Alo,
                    const __half* __restrict__ Bhi,
                    float* __restrict__ C, int M, int N, int K, float outScale)
{
    extern __shared__ __half smem[];
    const unsigned smbase = smaddr_of(smem);

    const int tid  = threadIdx.x;
    const int wid  = tid >> 5;
    const int lane = tid & 31;
    const int g    = lane >> 2;
    const int tg   = lane & 3;
    const int wm   = (wid >> 1) * 32;
    const int wn   = (wid & 1) * 64;

    // ldmatrix per-lane addressing (elements)
    const int arow  = wm + (lane & 15);
    const int acol8 = (lane >> 4) * 8;
    const int brow  = wn + ((lane >> 4) & 1) * 8 + (lane & 7);
    const int bk8   = ((lane >> 3) & 1) * 8;

    const __half* A0 = Ahi + (size_t)(blockIdx.y * 128) * K;
    const __half* A1 = Alo + (size_t)(blockIdx.y * 128) * K;
    const __half* B0 = Bhi + (size_t)(blockIdx.x * 128) * K;

    float acc[2][8][4];
#pragma unroll
    for (int mt = 0; mt < 2; mt++)
#pragma unroll
        for (int nt = 0; nt < 8; nt++)
#pragma unroll
            for (int j = 0; j < 4; j++) acc[mt][nt][j] = 0.f;

    stage_load2(A0, A1, B0, smem, tid, K, 0);
    asm volatile("cp.async.commit_group;");

    const int nT = K >> 5;
    for (int t = 0; t < nT; t++) {
        if (t + 1 < nT) {
            stage_load2(A0, A1, B0, smem + ((t + 1) & 1) * STAGE2, tid, K, t + 1);
            asm volatile("cp.async.commit_group;");
            asm volatile("cp.async.wait_group 1;");
        } else {
            asm volatile("cp.async.wait_group 0;");
        }
        __syncthreads();

        const unsigned stageb = smbase + (unsigned)((t & 1) * STAGE2 * 2);

#pragma unroll
        for (int ks = 0; ks < 2; ks++) {
            uint32_t aH[2][4], aL[2][4];
#pragma unroll
            for (int mt = 0; mt < 2; mt++) {
                const unsigned ao = stageb + 2u * (unsigned)((arow + mt * 16) * GPAD + ks * 16 + acol8);
                LDSM_X4(aH[mt][0], aH[mt][1], aH[mt][2], aH[mt][3], ao);
                LDSM_X4(aL[mt][0], aL[mt][1], aL[mt][2], aL[mt][3], ao + 2u * SEC);
            }
#pragma unroll
            for (int p = 0; p < 4; p++) {
                uint32_t b0, b1, b2, b3;
                const unsigned bo = stageb + 4u * SEC +
                    2u * (unsigned)((brow + p * 16) * GPAD + ks * 16 + bk8);
                LDSM_X4(b0, b1, b2, b3, bo);
#pragma unroll
                for (int mt = 0; mt < 2; mt++) {
                    MMA_FP16(acc[mt][2 * p],     aH[mt], b0, b1);
                    MMA_FP16(acc[mt][2 * p],     aL[mt], b0, b1);
                    MMA_FP16(acc[mt][2 * p + 1], aH[mt], b2, b3);
                    MMA_FP16(acc[mt][2 * p + 1], aL[mt], b2, b3);
                }
            }
        }
        __syncthreads();
    }

    float* Cb = C + (size_t)(blockIdx.y * 128 + wm) * N + blockIdx.x * 128 + wn;
#pragma unroll
    for (int mt = 0; mt < 2; mt++)
#pragma unroll
        for (int nt = 0; nt < 8; nt++) {
            const int col = nt * 8 + tg * 2;
            *(float2*)&Cb[(size_t)(mt * 16 + g) * N + col] = make_float2(
                acc[mt][nt][0] * outScale, acc[mt][nt][1] * outScale);
            *(float2*)&Cb[(size_t)(mt * 16 + g + 8) * N + col] = make_float2(
                acc[mt][nt][2] * outScale, acc[mt][nt][3] * outScale);
        }
}

// ---- 3-pass variant (B also split hi/lo) — used for the K projection ----
__device__ __forceinline__ void stage_load3(
    const __half* Ahi, const __half* Alo, const __half* Bhi, const __half* Blo,
    __half* sm, int tid, int K, int t)
{
#pragma unroll
    for (int i = 0; i < 2; i++) {
        const int idx = tid + i * 256;
        const int r   = idx >> 2;
        const int c8  = (idx & 3) * 8;
        const size_t goff = (size_t)r * K + (size_t)t * 32 + c8;
        const int soff = r * GPAD + c8;
        cpasync16(smaddr_of(sm + soff),           Ahi + goff);
        cpasync16(smaddr_of(sm + SEC + soff),     Alo + goff);
        cpasync16(smaddr_of(sm + 2 * SEC + soff), Bhi + goff);
        cpasync16(smaddr_of(sm + 3 * SEC + soff), Blo + goff);
    }
}

__global__ __launch_bounds__(256)
void fp16split3_gemm(const __half* __restrict__ Ahi, const __half* __restrict__ Alo,
                     const __half* __restrict__ Bhi, const __half* __restrict__ Blo,
                     float* __restrict__ C, int M, int N, int K)
{
    extern __shared__ __half smem[];
    const unsigned smbase = smaddr_of(smem);

    const int tid  = threadIdx.x;
    const int wid  = tid >> 5;
    const int lane = tid & 31;
    const int g    = lane >> 2;
    const int tg   = lane & 3;
    const int wm   = (wid >> 1) * 32;
    const int wn   = (wid & 1) * 64;

    const int arow  = wm + (lane & 15);
    const int acol8 = (lane >> 4) * 8;
    const int brow  = wn + ((lane >> 4) & 1) * 8 + (lane & 7);
    const int bk8   = ((lane >> 3) & 1) * 8;

    const __half* A0 = Ahi + (size_t)(blockIdx.y * 128) * K;
    const __half* A1 = Alo + (size_t)(blockIdx.y * 128) * K;
    const __half* B0 = Bhi + (size_t)(blockIdx.x * 128) * K;
    const __half* B1 = Blo + (size_t)(blockIdx.x * 128) * K;

    float acc[2][8][4];
#pragma unroll
    for (int mt = 0; mt < 2; mt++)
#pragma unroll
        for (int nt = 0; nt < 8; nt++)
#pragma unroll
            for (int j = 0; j < 4; j++) acc[mt][nt][j] = 0.f;

    stage_load3(A0, A1, B0, B1, smem, tid, K, 0);
    asm volatile("cp.async.commit_group;");

    const int nT = K >> 5;
    for (int t = 0; t < nT; t++) {
        if (t + 1 < nT) {
            stage_load3(A0, A1, B0, B1, smem + ((t + 1) & 1) * STAGE3, tid, K, t + 1);
            asm volatile("cp.async.commit_group;");
            asm volatile("cp.async.wait_group 1;");
        } else {
            asm volatile("cp.async.wait_group 0;");
        }
        __syncthreads();

        const unsigned stageb = smbase + (unsigned)((t & 1) * STAGE3 * 2);

#pragma unroll
        for (int ks = 0; ks < 2; ks++) {
            uint32_t aH[2][4], aL[2][4];
#pragma unroll
            for (int mt = 0; mt < 2; mt++) {
                const unsigned ao = stageb + 2u * (unsigned)((arow + mt * 16) * GPAD + ks * 16 + acol8);
                LDSM_X4(aH[mt][0], aH[mt][1], aH[mt][2], aH[mt][3], ao);
                LDSM_X4(aL[mt][0], aL[mt][1], aL[mt][2], aL[mt][3], ao + 2u * SEC);
            }
#pragma unroll
            for (int p = 0; p < 4; p++) {
                uint32_t bh0, bh1, bh2, bh3, bl0, bl1, bl2, bl3;
                const unsigned bo = stageb +
                    2u * (unsigned)((brow + p * 16) * GPAD + ks * 16 + bk8);
                LDSM_X4(bh0, bh1, bh2, bh3, bo + 4u * SEC);
                LDSM_X4(bl0, bl1, bl2, bl3, bo + 6u * SEC);
#pragma unroll
                for (int mt = 0; mt < 2; mt++) {
                    MMA_FP16(acc[mt][2 * p],     aH[mt], bh0, bh1);
                    MMA_FP16(acc[mt][2 * p],     aH[mt], bl0, bl1);
                    MMA_FP16(acc[mt][2 * p],     aL[mt], bh0, bh1);
                    MMA_FP16(acc[mt][2 * p + 1], aH[mt], bh2, bh3);
                    MMA_FP16(acc[mt][2 * p + 1], aH[mt], bl2, bl3);
                    MMA_FP16(acc[mt][2 * p + 1], aL[mt], bh2, bh3);
                }
            }
        }
        __syncthreads();
    }

    float* Cb = C + (size_t)(blockIdx.y * 128 + wm) * N + blockIdx.x * 128 + wn;
#pragma unroll
    for (int mt = 0; mt < 2; mt++)
#pragma unroll
        for (int nt = 0; nt < 8; nt++) {
            const int col = nt * 8 + tg * 2;
            *(float2*)&Cb[(size_t)(mt * 16 + g) * N + col] =
                make_float2(acc[mt][nt][0], acc[mt][nt][1]);
            *(float2*)&Cb[(size_t)(mt * 16 + g + 8) * N + col] =
                make_float2(acc[mt][nt][2], acc[mt][nt][3]);
        }
}

// ---------------- fp32 -> (hi, lo) fp16 split ----------------
__global__ void cvt_split_kernel(const float* __restrict__ in,
                                 __half* __restrict__ hi,
                                 __half* __restrict__ lo, int n4)
{
    const int i = blockIdx.x * 256 + threadIdx.x;
    if (i >= n4) return;
    const float4 x = ((const float4*)in)[i];
    union { __half b[4]; uint2 u; } H, L;
    float v[4] = {x.x, x.y, x.z, x.w};
#pragma unroll
    for (int j = 0; j < 4; j++) {
        const __half h = __float2half_rn(v[j]);
        H.b[j] = h;
        L.b[j] = __float2half_rn(v[j] - __half2float(h));
    }
    ((uint2*)hi)[i] = H.u;
    ((uint2*)lo)[i] = L.u;
}

// ---------------- weight transpose: fp32 [K][N] -> fp16 [N][K] ----------------
__global__ void wtrans_kernel(const float* __restrict__ W,
                              __half* __restrict__ Whi, int K, int N)
{
    __shared__ float tile[32][33];
    const int n0 = blockIdx.x * 32, k0 = blockIdx.y * 32;
    const int tx = threadIdx.x & 31, ty = threadIdx.x >> 5;
#pragma unroll
    for (int i = 0; i < 32; i += 8)
        tile[ty + i][tx] = W[(size_t)(k0 + ty + i) * N + n0 + tx];
    __syncthreads();
#pragma unroll
    for (int i = 0; i < 32; i += 8)
        Whi[(size_t)(n0 + ty + i) * K + k0 + tx] = __float2half_rn(tile[tx][ty + i]);
}

__global__ void wtrans2_kernel(const float* __restrict__ W,
                               __half* __restrict__ Whi,
                               __half* __restrict__ Wlo, int K, int N)
{
    __shared__ float tile[32][33];
    const int n0 = blockIdx.x * 32, k0 = blockIdx.y * 32;
    const int tx = threadIdx.x & 31, ty = threadIdx.x >> 5;
#pragma unroll
    for (int i = 0; i < 32; i += 8)
        tile[ty + i][tx] = W[(size_t)(k0 + ty + i) * N + n0 + tx];
    __syncthreads();
#pragma unroll
    for (int i = 0; i < 32; i += 8) {
        const float v = tile[tx][ty + i];
        const __half h = __float2half_rn(v);
        const size_t o = (size_t)(n0 + ty + i) * K + k0 + tx;
        Whi[o] = h;
        Wlo[o] = __float2half_rn(v - __half2float(h));
    }
}

// ---------------- RoPE + kappa, in place ----------------
__global__ void rope_kappa_kernel(float* __restrict__ x, int nheads, int total)
{
    const int idx = blockIdx.x * blockDim.x + threadIdx.x;
    if (idx >= total) return;
    const int i  = idx & 31;
    const int rh = idx >> 5;
    const int row = rh / nheads;
    const int s = row & (S_ - 1);

    const float inv = expf((float)i * -0.28782313662425573f);
    const float fr = (float)s * inv;
    float sn, cs;
    sincosf(fr, &sn, &cs);

    const size_t base = (size_t)rh * 64;
    const float x1 = x[base + i];
    const float x2 = x[base + i + 32];
    const float y1 = x1 * cs - x2 * sn;
    const float y2 = x2 * cs + x1 * sn;
    x[base + i]      = (y1 > 0.f) ? (y1 + 1.f) : expf(y1);
    x[base + i + 32] = (y2 > 0.f) ? (y2 + 1.f) : expf(y2);
}

// ---------------- Qg ----------------
__global__ void zero_qg_kernel()
{
    const int i = blockIdx.x * 256 + threadIdx.x;
    if (i < B_ * HID_) g_qg[i] = 0.f;
}

__global__ void qg_partial_kernel()  // grid (HID_/256, S_/256, B_)
{
    const int col = blockIdx.x * 256 + threadIdx.x;
    const int b   = blockIdx.z;
    const int r0  = blockIdx.y * 256;
    const float* base = g_q + ((size_t)(b * S_ + r0)) * HID_ + col;
    float s = 0.f;
#pragma unroll 8
    for (int r = 0; r < 256; r++) s += base[(size_t)r * HID_];
    atomicAdd(&g_qg[b * HID_ + col], s);
}

// ---------------- logits ----------------
__global__ void logits_kernel()      // <<<256,256>>>
{
    const int gt   = blockIdx.x * blockDim.x + threadIdx.x;
    const int warp = gt >> 5;
    const int lane = gt & 31;
    const int chunk = warp & 31;
    const int bh    = warp >> 5;
    const int h = bh & 31, b = bh >> 5;
    const int kv = h >> 2;

    float2 qv = *(const float2*)&g_qg[b * HID_ + h * 64 + lane * 2];
    const float sc = 1.0f / (float)S_;
    qv.x *= sc; qv.y *= sc;

    const float* kb = g_k + (size_t)b * S_ * KVW_ + kv * 64 + lane * 2;
    float* lb = g_log + (size_t)bh * S_;
    const int s0 = chunk * 128;
    for (int s = s0; s < s0 + 128; s++) {
        const float2 k2 = *(const float2*)(kb + (size_t)s * KVW_);
        float d = k2.x * qv.x + k2.y * qv.y;
#pragma unroll
        for (int o = 16; o > 0; o >>= 1) d += __shfl_xor_sync(0xffffffffu, d, o);
        if (lane == 0) lb[s] = d;
    }
}

// ---------------- softmax over S per (b,h), scaled by S, in place ----------------
__global__ __launch_bounds__(256)
void softmax_kernel()                // <<<64,256>>>
{
    __shared__ float buf[S_];
    __shared__ float red[256];
    float* row = g_log + (size_t)blockIdx.x * S_;
    const int t = threadIdx.x;

    float m = -1e30f;
    for (int i = t; i < S_; i += 256) { const float v = row[i]; buf[i] = v; m = fmaxf(m, v); }
    red[t] = m; __syncthreads();
    for (int st = 128; st > 0; st >>= 1) { if (t < st) red[t] = fmaxf(red[t], red[t + st]); __syncthreads(); }
    m = red[0]; __syncthreads();

    float sum = 0.f;
    for (int i = t; i < S_; i += 256) { const float e = expf(buf[i] - m); buf[i] = e; sum += e; }
    red[t] = sum; __syncthreads();
    for (int st = 128; st > 0; st >>= 1) { if (t < st) red[t] += red[t + st]; __syncthreads(); }
    const float inv = (float)S_ / red[0];
    for (int i = t; i < S_; i += 256) row[i] = buf[i] * inv;
}

// ---------------- state[b,h] (64x64) ----------------
__global__ __launch_bounds__(256)
void outer_kernel()                  // <<<64,256>>>
{
    const int bh = blockIdx.x;
    const int h = bh & 31, b = bh >> 5;
    const int kv = h >> 2;
    __shared__ float ks[32][64];
    __shared__ float vs[32][64];
    const int t = threadIdx.x;
    const int ti = t >> 4, tj = t & 15;
    float acc[4][4] = {};

    const float* kb = g_k + (size_t)b * S_ * KVW_ + kv * 64;
    const float* vb = g_v + (size_t)b * S_ * KVW_ + kv * 64;
    const float* ab = g_log + (size_t)bh * S_;

    for (int s0 = 0; s0 < S_; s0 += 32) {
#pragma unroll
        for (int rep = 0; rep < 2; rep++) {
            const int idx = t + rep * 256;
            const int r = idx >> 4;
            const int c = (idx & 15) << 2;
            const float a = ab[s0 + r];
            const float4 k4 = *(const float4*)(kb + (size_t)(s0 + r) * KVW_ + c);
            *(float4*)&ks[r][c] = make_float4(k4.x * a, k4.y * a, k4.z * a, k4.w * a);
            *(float4*)&vs[r][c] = *(const float4*)(vb + (size_t)(s0 + r) * KVW_ + c);
        }
        __syncthreads();
#pragma unroll
        for (int ss = 0; ss < 32; ss++) {
            float ka[4], vf[4];
            *(float4*)ka = *(const float4*)&ks[ss][ti * 4];
            *(float4*)vf = *(const float4*)&vs[ss][tj * 4];
#pragma unroll
            for (int i = 0; i < 4; i++)
#pragma unroll
                for (int j = 0; j < 4; j++)
                    acc[i][j] = fmaf(ka[i], vf[j], acc[i][j]);
        }
        __syncthreads();
    }
#pragma unroll
    for (int i = 0; i < 4; i++)
        *(float4*)&g_out[(size_t)bh * 4096 + (size_t)(ti * 4 + i) * 64 + tj * 4] =
            make_float4(acc[i][0], acc[i][1], acc[i][2], acc[i][3]);
}

// ---------------- ctx = phi * (Qk @ state) * CTX_SCALE -> split fp16 ----------------
__global__ __launch_bounds__(256)
void ctx_kernel()                    // grid (S_/64, NH_, B_)
{
    const int b = blockIdx.z, h = blockIdx.y, s0 = blockIdx.x * 64;
    __shared__ float Os[64][64];
    __shared__ float Qs[64][68];
    const int t = threadIdx.x;

    const float* ob = g_out + (size_t)(b * NH_ + h) * 4096;
#pragma unroll
    for (int rep = 0; rep < 4; rep++)
        ((float4*)&Os[0][0])[t + rep * 256] = ((const float4*)ob)[t + rep * 256];

    const float* qb = g_q + ((size_t)(b * S_ + s0)) * HID_ + h * 64;
#pragma unroll
    for (int rep = 0; rep < 4; rep++) {
        const int idx = t + rep * 256;
        const int r = idx >> 4;
        const int c = (idx & 15) << 2;
        *(float4*)&Qs[r][c] = *(const float4*)(qb + (size_t)r * HID_ + c);
    }
    __syncthreads();

    const int ti = t >> 4, tj = t & 15;
    float acc[4][4] = {};
#pragma unroll 4
    for (int d = 0; d < 64; d++) {
        float o[4];
        *(float4*)o = *(const float4*)&Os[d][tj * 4];
#pragma unroll
        for (int i = 0; i < 4; i++) {
            const float qv = Qs[ti * 4 + i][d];
#pragma unroll
            for (int j = 0; j < 4; j++)
                acc[i][j] = fmaf(qv, o[j], acc[i][j]);
        }
    }

    const float* pb = g_phi + ((size_t)(b * S_ + s0)) * HID_ + h * 64;
    __half* ph = g_phihi + ((size_t)(b * S_ + s0)) * HID_ + h * 64;
    __half* pl = g_philo + ((size_t)(b * S_ + s0)) * HID_ + h * 64;
#pragma unroll
    for (int i = 0; i < 4; i++) {
        const size_t off = (size_t)(ti * 4 + i) * HID_ + tj * 4;
        const float4 p = *(const float4*)(pb + off);
        float r[4] = {p.x * acc[i][0] * CTX_SCALE, p.y * acc[i][1] * CTX_SCALE,
                      p.z * acc[i][2] * CTX_SCALE, p.w * acc[i][3] * CTX_SCALE};
        union { __half b[4]; uint2 u; } H, L;
#pragma unroll
        for (int j = 0; j < 4; j++) {
            const __half hh = __float2half_rn(r[j]);
            H.b[j] = hh;
            L.b[j] = __float2half_rn(r[j] - __half2float(hh));
        }
        *(uint2*)(ph + off) = H.u;
        *(uint2*)(pl + off) = L.u;
    }
}

// ---------------- launch ----------------
extern "C" void kernel_launch(void* const* d_in, const int* in_sizes, int n_in,
                              void* d_out, int out_size)
{
    const float* X   = (const float*)d_in[0];
    const float* Wq  = (const float*)d_in[1];
    const float* Wk  = (const float*)d_in[2];
    const float* Wv  = (const float*)d_in[3];
    const float* Wph = (const float*)d_in[4];
    const float* Wo  = (const float*)d_in[5];
    float* out = (float*)d_out;

    float *q, *k, *v, *ph;
    __half *xhi, *xlo, *whi, *wklo, *phihi, *philo;
    cudaGetSymbolAddress((void**)&q,     g_q);
    cudaGetSymbolAddress((void**)&k,     g_k);
    cudaGetSymbolAddress((void**)&v,     g_v);
    cudaGetSymbolAddress((void**)&ph,    g_phi);
    cudaGetSymbolAddress((void**)&xhi,   g_xhi);
    cudaGetSymbolAddress((void**)&xlo,   g_xlo);
    cudaGetSymbolAddress((void**)&whi,   g_whi);
    cudaGetSymbolAddress((void**)&wklo,  g_wklo);
    cudaGetSymbolAddress((void**)&phihi, g_phihi);
    cudaGetSymbolAddress((void**)&philo, g_philo);

    cudaFuncSetAttribute(fp16split_gemm,
                         cudaFuncAttributeMaxDynamicSharedMemorySize, SMEM2);
    cudaFuncSetAttribute(fp16split3_gemm,
                         cudaFuncAttributeMaxDynamicSharedMemorySize, SMEM3);

    // Split X (hi/lo fp16); transpose+quantize weights ([N][K] fp16; Wk keeps lo)
    cvt_split_kernel<<<(ROWS_ * HID_ / 4 + 255) / 256, 256>>>(X, xhi, xlo, ROWS_ * HID_ / 4);
    wtrans_kernel <<<dim3(HID_ / 32, HID_ / 32), 256>>>(Wq,  whi + WQOFF, HID_, HID_);
    wtrans2_kernel<<<dim3(KVW_ / 32, HID_ / 32), 256>>>(Wk,  whi + WKOFF, wklo, HID_, KVW_);
    wtrans_kernel <<<dim3(KVW_ / 32, HID_ / 32), 256>>>(Wv,  whi + WVOFF, HID_, KVW_);
    wtrans_kernel <<<dim3(HID_ / 32, HID_ / 32), 256>>>(Wph, whi + WPOFF, HID_, HID_);
    wtrans_kernel <<<dim3(HID_ / 32, HID_ / 32), 256>>>(Wo,  whi + WOOFF, HID_, HID_);

    // Projections: 2-pass for Q/V/phi, 3-pass for K (softmax-sensitive)
    fp16split_gemm<<<dim3(HID_ / 128, ROWS_ / 128), 256, SMEM2>>>(
        xhi, xlo, whi + WQOFF, q,  ROWS_, HID_, HID_, 1.0f);
    fp16split3_gemm<<<dim3(KVW_ / 128, ROWS_ / 128), 256, SMEM3>>>(
        xhi, xlo, whi + WKOFF, wklo, k, ROWS_, KVW_, HID_);
    fp16split_gemm<<<dim3(KVW_ / 128, ROWS_ / 128), 256, SMEM2>>>(
        xhi, xlo, whi + WVOFF, v,  ROWS_, KVW_, HID_, 1.0f);
    fp16split_gemm<<<dim3(HID_ / 128, ROWS_ / 128), 256, SMEM2>>>(
        xhi, xlo, whi + WPOFF, ph, ROWS_, HID_, HID_, 1.0f);

    // RoPE + kappa (in place)
    rope_kappa_kernel<<<(ROWS_ * NH_  * 32) / 256, 256>>>(q, NH_,  ROWS_ * NH_  * 32);
    rope_kappa_kernel<<<(ROWS_ * NKV_ * 32) / 256, 256>>>(k, NKV_, ROWS_ * NKV_ * 32);

    // Global query mean (sum; 1/S folded into logits)
    zero_qg_kernel<<<(B_ * HID_ + 255) / 256, 256>>>();
    qg_partial_kernel<<<dim3(HID_ / 256, S_ / 256, B_), 256>>>();

    // logits -> alpha -> state
    logits_kernel<<<256, 256>>>();
    softmax_kernel<<<B_ * NH_, 256>>>();
    outer_kernel<<<B_ * NH_, 256>>>();

    // ctx = phi*(Qk@state)*2^-10 -> split fp16, then Wo GEMM rescales by 2^10
    ctx_kernel<<<dim3(S_ / 64, NH_, B_), 256>>>();
    fp16split_gemm<<<dim3(HID_ / 128, ROWS_ / 128), 256, SMEM2>>>(
        phihi, philo, whi + WOOFF, out, ROWS_, HID_, HID_, CTX_UNSCALE);
}

// round 11
// speedup vs baseline: 1.6424x; 1.6424x over previous
#include <cuda_runtime.h>
#include <cuda_fp16.h>
#include <math.h>
#include <stdint.h>

#define B_    2
#define S_    4096
#define HID_  2048
#define NH_   32
#define NKV_  8
#define HD_   64
#define ROWS_ (B_ * S_)          /* 8192 */
#define KVW_  (NKV_ * HD_)       /* 512  */

#define CTX_SCALE   (1.0f / 1024.0f)
#define CTX_UNSCALE 1024.0f

// weight offsets in the combined transposed-weight buffer (elements)
#define WQOFF 0
#define WKOFF (2048 * 2048)
#define WVOFF (WKOFF + 512 * 2048)
#define WPOFF (WVOFF + 512 * 2048)
#define WOOFF (WPOFF + 2048 * 2048)
#define WTOT  (WOOFF + 2048 * 2048)   /* 7168 * 2048 */

// ---------------- device scratch (no allocs allowed) ----------------
__device__ float g_q  [(size_t)ROWS_ * HID_];
__device__ float g_k  [(size_t)ROWS_ * KVW_];
__device__ float g_v  [(size_t)ROWS_ * KVW_];
__device__ float g_phi[(size_t)ROWS_ * HID_];
__device__ float g_qg [B_ * HID_];
__device__ float g_log[B_ * NH_ * S_];
__device__ float g_out[B_ * NH_ * HD_ * HD_];

__device__ __half g_xhi [(size_t)ROWS_ * HID_];
__device__ __half g_xlo [(size_t)ROWS_ * HID_];
__device__ __half g_whi [(size_t)WTOT];
__device__ __half g_wklo[(size_t)KVW_ * HID_];   // lo part for Wk only
__device__ __half g_phihi[(size_t)ROWS_ * HID_];
__device__ __half g_philo[(size_t)ROWS_ * HID_];

// ================= split-fp16 tensor-core GEMM =================
// 2-pass: C = (Ahi+Alo) @ Bhi^T * outScale      (exact A, fp16-quantized B)
//   3-stage cp.async pipeline, ONE __syncthreads per BK iter.
// 3-pass: C = (Ahi+Alo) @ (Bhi+Blo)^T           (exact A, ~fp32 B; for Wk)
//   2-stage (round-9 proven path; only ~7% of GEMM work).
// Block 128x128, BK=32, 8 warps (warp tile 32x64).

#define GPAD 40                 // smem row stride in fp16 elems (conflict-free)
#define SEC  (128 * GPAD)       // 5120 elems per component tile
#define STAGE2 (3 * SEC)        // Ahi, Alo, Bhi
#define SMEM2  (3 * STAGE2 * 2) /* 92160: 3 stages */
#define STAGE3 (4 * SEC)        // Ahi, Alo, Bhi, Blo
#define SMEM3  (2 * STAGE3 * 2) /* 81920: 2 stages */

__device__ __forceinline__ void cpasync16(unsigned smaddr, const void* g) {
    asm volatile("cp.async.cg.shared.global [%0], [%1], 16;" :: "r"(smaddr), "l"(g));
}

__device__ __forceinline__ unsigned smaddr_of(const void* p) {
    return (unsigned)__cvta_generic_to_shared(p);
}

#define MMA_FP16(c, a, b0, b1)                                              \
    asm volatile("mma.sync.aligned.m16n8k16.row.col.f32.f16.f16.f32 "       \
                 "{%0,%1,%2,%3}, {%4,%5,%6,%7}, {%8,%9}, {%0,%1,%2,%3};"    \
                 : "+f"(c[0]), "+f"(c[1]), "+f"(c[2]), "+f"(c[3])           \
                 : "r"(a[0]), "r"(a[1]), "r"(a[2]), "r"(a[3]),              \
                   "r"(b0), "r"(b1))

__device__ __forceinline__ void stage_load2(
    const __half* Ahi, const __half* Alo, const __half* Bhi,
    __half* sm, int tid, int K, int t)
{
#pragma unroll
    for (int i = 0; i < 2; i++) {
        const int idx = tid + i * 256;
        const int r   = idx >> 2;
        const int c8  = (idx & 3) * 8;
        const size_t goff = (size_t)r * K + (size_t)t * 32 + c8;
        const int soff = r * GPAD + c8;
        cpasync16(smaddr_of(sm + soff),           Ahi + goff);
        cpasync16(smaddr_of(sm + SEC + soff),     Alo + goff);
        cpasync16(smaddr_of(sm + 2 * SEC + soff), Bhi + goff);
    }
}

__global__ __launch_bounds__(256)
void fp16split_gemm(const __half* __restrict__ Ahi, const __half* __restrict__ Alo,
                    const __half* __restrict__ Bhi,
                    float* __restrict__ C, int M, int N, int K, float outScale)
{
    extern __shared__ __half smem[];

    const int tid  = threadIdx.x;
    const int wid  = tid >> 5;
    const int lane = tid & 31;
    const int g    = lane >> 2;
    const int tg   = lane & 3;
    const int wm   = (wid >> 1) * 32;
    const int wn   = (wid & 1) * 64;

    const __half* A0 = Ahi + (size_t)(blockIdx.y * 128) * K;
    const __half* A1 = Alo + (size_t)(blockIdx.y * 128) * K;
    const __half* B0 = Bhi + (size_t)(blockIdx.x * 128) * K;

    float acc[2][8][4];
#pragma unroll
    for (int mt = 0; mt < 2; mt++)
#pragma unroll
        for (int nt = 0; nt < 8; nt++)
#pragma unroll
            for (int j = 0; j < 4; j++) acc[mt][nt][j] = 0.f;

    const int nT = K >> 5;   // >= 16 for all our shapes

    // prologue: prefetch stages 0 and 1
    stage_load2(A0, A1, B0, smem, tid, K, 0);
    asm volatile("cp.async.commit_group;");
    stage_load2(A0, A1, B0, smem + STAGE2, tid, K, 1);
    asm volatile("cp.async.commit_group;");

    int cur = 0;                 // t % 3
    for (int t = 0; t < nT; t++) {
        if (t + 1 < nT) {
            asm volatile("cp.async.wait_group 1;");
        } else {
            asm volatile("cp.async.wait_group 0;");
        }
        __syncthreads();

        const uint32_t* sA0 = (const uint32_t*)(smem + cur * STAGE2);
        const uint32_t* sA1 = sA0 + SEC / 2;
        const uint32_t* sB0 = sA0 + SEC;

#pragma unroll
        for (int ks = 0; ks < 2; ks++) {
            uint32_t aH[2][4], aL[2][4];
#pragma unroll
            for (int mt = 0; mt < 2; mt++) {
                const int r0 = (wm + mt * 16 + g) * 20 + ks * 8 + tg;
                const int r1 = r0 + 8 * 20;
                aH[mt][0] = sA0[r0];     aH[mt][1] = sA0[r1];
                aH[mt][2] = sA0[r0 + 4]; aH[mt][3] = sA0[r1 + 4];
                aL[mt][0] = sA1[r0];     aL[mt][1] = sA1[r1];
                aL[mt][2] = sA1[r0 + 4]; aL[mt][3] = sA1[r1 + 4];
            }
#pragma unroll
            for (int nt = 0; nt < 8; nt++) {
                const int nb = (wn + nt * 8 + g) * 20 + ks * 8 + tg;
                const uint32_t bH0 = sB0[nb], bH1 = sB0[nb + 4];
#pragma unroll
                for (int mt = 0; mt < 2; mt++) {
                    MMA_FP16(acc[mt][nt], aH[mt], bH0, bH1);
                    MMA_FP16(acc[mt][nt], aL[mt], bH0, bH1);
                }
            }
        }

        // prefetch t+2 into buffer (t+2)%3 == (t-1)%3; all readers of that
        // buffer passed this iteration's __syncthreads already.
        if (t + 2 < nT) {
            const int nxt = (cur + 2 >= 3) ? cur - 1 : cur + 2;
            stage_load2(A0, A1, B0, smem + nxt * STAGE2, tid, K, t + 2);
            asm volatile("cp.async.commit_group;");
        }
        cur = (cur == 2) ? 0 : cur + 1;
    }

    float* Cb = C + (size_t)(blockIdx.y * 128 + wm) * N + blockIdx.x * 128 + wn;
#pragma unroll
    for (int mt = 0; mt < 2; mt++)
#pragma unroll
        for (int nt = 0; nt < 8; nt++) {
            const int col = nt * 8 + tg * 2;
            *(float2*)&Cb[(size_t)(mt * 16 + g) * N + col] = make_float2(
                acc[mt][nt][0] * outScale, acc[mt][nt][1] * outScale);
            *(float2*)&Cb[(size_t)(mt * 16 + g + 8) * N + col] = make_float2(
                acc[mt][nt][2] * outScale, acc[mt][nt][3] * outScale);
        }
}

// ---- 3-pass variant (B also split hi/lo) — used for the K projection ----
__device__ __forceinline__ void stage_load3(
    const __half* Ahi, const __half* Alo, const __half* Bhi, const __half* Blo,
    __half* sm, int tid, int K, int t)
{
#pragma unroll
    for (int i = 0; i < 2; i++) {
        const int idx = tid + i * 256;
        const int r   = idx >> 2;
        const int c8  = (idx & 3) * 8;
        const size_t goff = (size_t)r * K + (size_t)t * 32 + c8;
        const int soff = r * GPAD + c8;
        cpasync16(smaddr_of(sm + soff),           Ahi + goff);
        cpasync16(smaddr_of(sm + SEC + soff),     Alo + goff);
        cpasync16(smaddr_of(sm + 2 * SEC + soff), Bhi + goff);
        cpasync16(smaddr_of(sm + 3 * SEC + soff), Blo + goff);
    }
}

__global__ __launch_bounds__(256)
void fp16split3_gemm(const __half* __restrict__ Ahi, const __half* __restrict__ Alo,
                     const __half* __restrict__ Bhi, const __half* __restrict__ Blo,
                     float* __restrict__ C, int M, int N, int K)
{
    extern __shared__ __half smem[];

    const int tid  = threadIdx.x;
    const int wid  = tid >> 5;
    const int lane = tid & 31;
    const int g    = lane >> 2;
    const int tg   = lane & 3;
    const int wm   = (wid >> 1) * 32;
    const int wn   = (wid & 1) * 64;

    const __half* A0 = Ahi + (size_t)(blockIdx.y * 128) * K;
    const __half* A1 = Alo + (size_t)(blockIdx.y * 128) * K;
    const __half* B0 = Bhi + (size_t)(blockIdx.x * 128) * K;
    const __half* B1 = Blo + (size_t)(blockIdx.x * 128) * K;

    float acc[2][8][4];
#pragma unroll
    for (int mt = 0; mt < 2; mt++)
#pragma unroll
        for (int nt = 0; nt < 8; nt++)
#pragma unroll
            for (int j = 0; j < 4; j++) acc[mt][nt][j] = 0.f;

    stage_load3(A0, A1, B0, B1, smem, tid, K, 0);
    asm volatile("cp.async.commit_group;");

    const int nT = K >> 5;
    for (int t = 0; t < nT; t++) {
        if (t + 1 < nT) {
            stage_load3(A0, A1, B0, B1, smem + ((t + 1) & 1) * STAGE3, tid, K, t + 1);
            asm volatile("cp.async.commit_group;");
            asm volatile("cp.async.wait_group 1;");
        } else {
            asm volatile("cp.async.wait_group 0;");
        }
        __syncthreads();

        const uint32_t* sA0 = (const uint32_t*)(smem + (t & 1) * STAGE3);
        const uint32_t* sA1 = sA0 + SEC / 2;
        const uint32_t* sB0 = sA0 + SEC;
        const uint32_t* sB1 = sA0 + 3 * (SEC / 2);

#pragma unroll
        for (int ks = 0; ks < 2; ks++) {
            uint32_t aH[2][4], aL[2][4];
#pragma unroll
            for (int mt = 0; mt < 2; mt++) {
                const int r0 = (wm + mt * 16 + g) * 20 + ks * 8 + tg;
                const int r1 = r0 + 8 * 20;
                aH[mt][0] = sA0[r0];     aH[mt][1] = sA0[r1];
                aH[mt][2] = sA0[r0 + 4]; aH[mt][3] = sA0[r1 + 4];
                aL[mt][0] = sA1[r0];     aL[mt][1] = sA1[r1];
                aL[mt][2] = sA1[r0 + 4]; aL[mt][3] = sA1[r1 + 4];
            }
#pragma unroll
            for (int nt = 0; nt < 8; nt++) {
                const int nb = (wn + nt * 8 + g) * 20 + ks * 8 + tg;
                const uint32_t bH0 = sB0[nb], bH1 = sB0[nb + 4];
                const uint32_t bL0 = sB1[nb], bL1 = sB1[nb + 4];
#pragma unroll
                for (int mt = 0; mt < 2; mt++) {
                    MMA_FP16(acc[mt][nt], aH[mt], bH0, bH1);
                    MMA_FP16(acc[mt][nt], aH[mt], bL0, bL1);
                    MMA_FP16(acc[mt][nt], aL[mt], bH0, bH1);
                }
            }
        }
        __syncthreads();
    }

    float* Cb = C + (size_t)(blockIdx.y * 128 + wm) * N + blockIdx.x * 128 + wn;
#pragma unroll
    for (int mt = 0; mt < 2; mt++)
#pragma unroll
        for (int nt = 0; nt < 8; nt++) {
            const int col = nt * 8 + tg * 2;
            *(float2*)&Cb[(size_t)(mt * 16 + g) * N + col] =
                make_float2(acc[mt][nt][0], acc[mt][nt][1]);
            *(float2*)&Cb[(size_t)(mt * 16 + g + 8) * N + col] =
                make_float2(acc[mt][nt][2], acc[mt][nt][3]);
        }
}

// ---------------- fp32 -> (hi, lo) fp16 split ----------------
__global__ void cvt_split_kernel(const float* __restrict__ in,
                                 __half* __restrict__ hi,
                                 __half* __restrict__ lo, int n4)
{
    const int i = blockIdx.x * 256 + threadIdx.x;
    if (i >= n4) return;
    const float4 x = ((const float4*)in)[i];
    union { __half b[4]; uint2 u; } H, L;
    float v[4] = {x.x, x.y, x.z, x.w};
#pragma unroll
    for (int j = 0; j < 4; j++) {
        const __half h = __float2half_rn(v[j]);
        H.b[j] = h;
        L.b[j] = __float2half_rn(v[j] - __half2float(h));
    }
    ((uint2*)hi)[i] = H.u;
    ((uint2*)lo)[i] = L.u;
}

// ---------------- weight transpose: fp32 [K][N] -> fp16 [N][K] ----------------
__global__ void wtrans_kernel(const float* __restrict__ W,
                              __half* __restrict__ Whi, int K, int N)
{
    __shared__ float tile[32][33];
    const int n0 = blockIdx.x * 32, k0 = blockIdx.y * 32;
    const int tx = threadIdx.x & 31, ty = threadIdx.x >> 5;
#pragma unroll
    for (int i = 0; i < 32; i += 8)
        tile[ty + i][tx] = W[(size_t)(k0 + ty + i) * N + n0 + tx];
    __syncthreads();
#pragma unroll
    for (int i = 0; i < 32; i += 8)
        Whi[(size_t)(n0 + ty + i) * K + k0 + tx] = __float2half_rn(tile[tx][ty + i]);
}

__global__ void wtrans2_kernel(const float* __restrict__ W,
                               __half* __restrict__ Whi,
                               __half* __restrict__ Wlo, int K, int N)
{
    __shared__ float tile[32][33];
    const int n0 = blockIdx.x * 32, k0 = blockIdx.y * 32;
    const int tx = threadIdx.x & 31, ty = threadIdx.x >> 5;
#pragma unroll
    for (int i = 0; i < 32; i += 8)
        tile[ty + i][tx] = W[(size_t)(k0 + ty + i) * N + n0 + tx];
    __syncthreads();
#pragma unroll
    for (int i = 0; i < 32; i += 8) {
        const float v = tile[tx][ty + i];
        const __half h = __float2half_rn(v);
        const size_t o = (size_t)(n0 + ty + i) * K + k0 + tx;
        Whi[o] = h;
        Wlo[o] = __float2half_rn(v - __half2float(h));
    }
}

// ---------------- RoPE + kappa, in place ----------------
__global__ void rope_kappa_kernel(float* __restrict__ x, int nheads, int total)
{
    const int idx = blockIdx.x * blockDim.x + threadIdx.x;
    if (idx >= total) return;
    const int i  = idx & 31;
    const int rh = idx >> 5;
    const int row = rh / nheads;
    const int s = row & (S_ - 1);

    const float inv = expf((float)i * -0.28782313662425573f);
    const float fr = (float)s * inv;
    float sn, cs;
    sincosf(fr, &sn, &cs);

    const size_t base = (size_t)rh * 64;
    const float x1 = x[base + i];
    const float x2 = x[base + i + 32];
    const float y1 = x1 * cs - x2 * sn;
    const float y2 = x2 * cs + x1 * sn;
    x[base + i]      = (y1 > 0.f) ? (y1 + 1.f) : expf(y1);
    x[base + i + 32] = (y2 > 0.f) ? (y2 + 1.f) : expf(y2);
}

// ---------------- Qg ----------------
__global__ void zero_qg_kernel()
{
    const int i = blockIdx.x * 256 + threadIdx.x;
    if (i < B_ * HID_) g_qg[i] = 0.f;
}

__global__ void qg_partial_kernel()  // grid (HID_/256, S_/256, B_)
{
    const int col = blockIdx.x * 256 + threadIdx.x;
    const int b   = blockIdx.z;
    const int r0  = blockIdx.y * 256;
    const float* base = g_q + ((size_t)(b * S_ + r0)) * HID_ + col;
    float s = 0.f;
#pragma unroll 8
    for (int r = 0; r < 256; r++) s += base[(size_t)r * HID_];
    atomicAdd(&g_qg[b * HID_ + col], s);
}

// ---------------- logits ----------------
__global__ void logits_kernel()      // <<<256,256>>>
{
    const int gt   = blockIdx.x * blockDim.x + threadIdx.x;
    const int warp = gt >> 5;
    const int lane = gt & 31;
    const int chunk = warp & 31;
    const int bh    = warp >> 5;
    const int h = bh & 31, b = bh >> 5;
    const int kv = h >> 2;

    float2 qv = *(const float2*)&g_qg[b * HID_ + h * 64 + lane * 2];
    const float sc = 1.0f / (float)S_;
    qv.x *= sc; qv.y *= sc;

    const float* kb = g_k + (size_t)b * S_ * KVW_ + kv * 64 + lane * 2;
    float* lb = g_log + (size_t)bh * S_;
    const int s0 = chunk * 128;
    for (int s = s0; s < s0 + 128; s++) {
        const float2 k2 = *(const float2*)(kb + (size_t)s * KVW_);
        float d = k2.x * qv.x + k2.y * qv.y;
#pragma unroll
        for (int o = 16; o > 0; o >>= 1) d += __shfl_xor_sync(0xffffffffu, d, o);
        if (lane == 0) lb[s] = d;
    }
}

// ---------------- softmax over S per (b,h), scaled by S, in place ----------------
__global__ __launch_bounds__(256)
void softmax_kernel()                // <<<64,256>>>
{
    __shared__ float buf[S_];
    __shared__ float red[256];
    float* row = g_log + (size_t)blockIdx.x * S_;
    const int t = threadIdx.x;

    float m = -1e30f;
    for (int i = t; i < S_; i += 256) { const float v = row[i]; buf[i] = v; m = fmaxf(m, v); }
    red[t] = m; __syncthreads();
    for (int st = 128; st > 0; st >>= 1) { if (t < st) red[t] = fmaxf(red[t], red[t + st]); __syncthreads(); }
    m = red[0]; __syncthreads();

    float sum = 0.f;
    for (int i = t; i < S_; i += 256) { const float e = expf(buf[i] - m); buf[i] = e; sum += e; }
    red[t] = sum; __syncthreads();
    for (int st = 128; st > 0; st >>= 1) { if (t < st) red[t] += red[t + st]; __syncthreads(); }
    const float inv = (float)S_ / red[0];
    for (int i = t; i < S_; i += 256) row[i] = buf[i] * inv;
}

// ---------------- state[b,h] (64x64) ----------------
__global__ __launch_bounds__(256)
void outer_kernel()                  // <<<64,256>>>
{
    const int bh = blockIdx.x;
    const int h = bh & 31, b = bh >> 5;
    const int kv = h >> 2;
    __shared__ float ks[32][64];
    __shared__ float vs[32][64];
    const int t = threadIdx.x;
    const int ti = t >> 4, tj = t & 15;
    float acc[4][4] = {};

    const float* kb = g_k + (size_t)b * S_ * KVW_ + kv * 64;
    const float* vb = g_v + (size_t)b * S_ * KVW_ + kv * 64;
    const float* ab = g_log + (size_t)bh * S_;

    for (int s0 = 0; s0 < S_; s0 += 32) {
#pragma unroll
        for (int rep = 0; rep < 2; rep++) {
            const int idx = t + rep * 256;
            const int r = idx >> 4;
            const int c = (idx & 15) << 2;
            const float a = ab[s0 + r];
            const float4 k4 = *(const float4*)(kb + (size_t)(s0 + r) * KVW_ + c);
            *(float4*)&ks[r][c] = make_float4(k4.x * a, k4.y * a, k4.z * a, k4.w * a);
            *(float4*)&vs[r][c] = *(const float4*)(vb + (size_t)(s0 + r) * KVW_ + c);
        }
        __syncthreads();
#pragma unroll
        for (int ss = 0; ss < 32; ss++) {
            float ka[4], vf[4];
            *(float4*)ka = *(const float4*)&ks[ss][ti * 4];
            *(float4*)vf = *(const float4*)&vs[ss][tj * 4];
#pragma unroll
            for (int i = 0; i < 4; i++)
#pragma unroll
                for (int j = 0; j < 4; j++)
                    acc[i][j] = fmaf(ka[i], vf[j], acc[i][j]);
        }
        __syncthreads();
    }
#pragma unroll
    for (int i = 0; i < 4; i++)
        *(float4*)&g_out[(size_t)bh * 4096 + (size_t)(ti * 4 + i) * 64 + tj * 4] =
            make_float4(acc[i][0], acc[i][1], acc[i][2], acc[i][3]);
}

// ---------------- ctx = phi * (Qk @ state) * CTX_SCALE -> split fp16 ----------------
__global__ __launch_bounds__(256)
void ctx_kernel()                    // grid (S_/64, NH_, B_)
{
    const int b = blockIdx.z, h = blockIdx.y, s0 = blockIdx.x * 64;
    __shared__ float Os[64][64];
    __shared__ float Qs[64][68];
    const int t = threadIdx.x;

    const float* ob = g_out + (size_t)(b * NH_ + h) * 4096;
#pragma unroll
    for (int rep = 0; rep < 4; rep++)
        ((float4*)&Os[0][0])[t + rep * 256] = ((const float4*)ob)[t + rep * 256];

    const float* qb = g_q + ((size_t)(b * S_ + s0)) * HID_ + h * 64;
#pragma unroll
    for (int rep = 0; rep < 4; rep++) {
        const int idx = t + rep * 256;
        const int r = idx >> 4;
        const int c = (idx & 15) << 2;
        *(float4*)&Qs[r][c] = *(const float4*)(qb + (size_t)r * HID_ + c);
    }
    __syncthreads();

    const int ti = t >> 4, tj = t & 15;
    float acc[4][4] = {};
#pragma unroll 4
    for (int d = 0; d < 64; d++) {
        float o[4];
        *(float4*)o = *(const float4*)&Os[d][tj * 4];
#pragma unroll
        for (int i = 0; i < 4; i++) {
            const float qv = Qs[ti * 4 + i][d];
#pragma unroll
            for (int j = 0; j < 4; j++)
                acc[i][j] = fmaf(qv, o[j], acc[i][j]);
        }
    }

    const float* pb = g_phi + ((size_t)(b * S_ + s0)) * HID_ + h * 64;
    __half* ph = g_phihi + ((size_t)(b * S_ + s0)) * HID_ + h * 64;
    __half* pl = g_philo + ((size_t)(b * S_ + s0)) * HID_ + h * 64;
#pragma unroll
    for (int i = 0; i < 4; i++) {
        const size_t off = (size_t)(ti * 4 + i) * HID_ + tj * 4;
        const float4 p = *(const float4*)(pb + off);
        float r[4] = {p.x * acc[i][0] * CTX_SCALE, p.y * acc[i][1] * CTX_SCALE,
                      p.z * acc[i][2] * CTX_SCALE, p.w * acc[i][3] * CTX_SCALE};
        union { __half b[4]; uint2 u; } H, L;
#pragma unroll
        for (int j = 0; j < 4; j++) {
            const __half hh = __float2half_rn(r[j]);
            H.b[j] = hh;
            L.b[j] = __float2half_rn(r[j] - __half2float(hh));
        }
        *(uint2*)(ph + off) = H.u;
        *(uint2*)(pl + off) = L.u;
    }
}

// ---------------- launch ----------------
extern "C" void kernel_launch(void* const* d_in, const int* in_sizes, int n_in,
                              void* d_out, int out_size)
{
    const float* X   = (const float*)d_in[0];
    const float* Wq  = (const float*)d_in[1];
    const float* Wk  = (const float*)d_in[2];
    const float* Wv  = (const float*)d_in[3];
    const float* Wph = (const float*)d_in[4];
    const float* Wo  = (const float*)d_in[5];
    float* out = (float*)d_out;

    float *q, *k, *v, *ph;
    __half *xhi, *xlo, *whi, *wklo, *phihi, *philo;
    cudaGetSymbolAddress((void**)&q,     g_q);
    cudaGetSymbolAddress((void**)&k,     g_k);
    cudaGetSymbolAddress((void**)&v,     g_v);
    cudaGetSymbolAddress((void**)&ph,    g_phi);
    cudaGetSymbolAddress((void**)&xhi,   g_xhi);
    cudaGetSymbolAddress((void**)&xlo,   g_xlo);
    cudaGetSymbolAddress((void**)&whi,   g_whi);
    cudaGetSymbolAddress((void**)&wklo,  g_wklo);
    cudaGetSymbolAddress((void**)&phihi, g_phihi);
    cudaGetSymbolAddress((void**)&philo, g_philo);

    cudaFuncSetAttribute(fp16split_gemm,
                         cudaFuncAttributeMaxDynamicSharedMemorySize, SMEM2);
    cudaFuncSetAttribute(fp16split3_gemm,
                         cudaFuncAttributeMaxDynamicSharedMemorySize, SMEM3);

    // Split X (hi/lo fp16); transpose+quantize weights ([N][K] fp16; Wk keeps lo)
    cvt_split_kernel<<<(ROWS_ * HID_ / 4 + 255) / 256, 256>>>(X, xhi, xlo, ROWS_ * HID_ / 4);
    wtrans_kernel <<<dim3(HID_ / 32, HID_ / 32), 256>>>(Wq,  whi + WQOFF, HID_, HID_);
    wtrans2_kernel<<<dim3(KVW_ / 32, HID_ / 32), 256>>>(Wk,  whi + WKOFF, wklo, HID_, KVW_);
    wtrans_kernel <<<dim3(KVW_ / 32, HID_ / 32), 256>>>(Wv,  whi + WVOFF, HID_, KVW_);
    wtrans_kernel <<<dim3(HID_ / 32, HID_ / 32), 256>>>(Wph, whi + WPOFF, HID_, HID_);
    wtrans_kernel <<<dim3(HID_ / 32, HID_ / 32), 256>>>(Wo,  whi + WOOFF, HID_, HID_);

    // Projections: 2-pass for Q/V/phi, 3-pass for K (softmax-sensitive)
    fp16split_gemm<<<dim3(HID_ / 128, ROWS_ / 128), 256, SMEM2>>>(
        xhi, xlo, whi + WQOFF, q,  ROWS_, HID_, HID_, 1.0f);
    fp16split3_gemm<<<dim3(KVW_ / 128, ROWS_ / 128), 256, SMEM3>>>(
        xhi, xlo, whi + WKOFF, wklo, k, ROWS_, KVW_, HID_);
    fp16split_gemm<<<dim3(KVW_ / 128, ROWS_ / 128), 256, SMEM2>>>(
        xhi, xlo, whi + WVOFF, v,  ROWS_, KVW_, HID_, 1.0f);
    fp16split_gemm<<<dim3(HID_ / 128, ROWS_ / 128), 256, SMEM2>>>(
        xhi, xlo, whi + WPOFF, ph, ROWS_, HID_, HID_, 1.0f);

    // RoPE + kappa (in place)
    rope_kappa_kernel<<<(ROWS_ * NH_  * 32) / 256, 256>>>(q, NH_,  ROWS_ * NH_  * 32);
    rope_kappa_kernel<<<(ROWS_ * NKV_ * 32) / 256, 256>>>(k, NKV_, ROWS_ * NKV_ * 32);

    // Global query mean (sum; 1/S folded into logits)
    zero_qg_kernel<<<(B_ * HID_ + 255) / 256, 256>>>();
    qg_partial_kernel<<<dim3(HID_ / 256, S_ / 256, B_), 256>>>();

    // logits -> alpha -> state
    logits_kernel<<<256, 256>>>();
    softmax_kernel<<<B_ * NH_, 256>>>();
    outer_kernel<<<B_ * NH_, 256>>>();

    // ctx = phi*(Qk@state)*2^-10 -> split fp16, then Wo GEMM rescales by 2^10
    ctx_kernel<<<dim3(S_ / 64, NH_, B_), 256>>>();
    fp16split_gemm<<<dim3(HID_ / 128, ROWS_ / 128), 256, SMEM2>>>(
        phihi, philo, whi + WOOFF, out, ROWS_, HID_, HID_, CTX_UNSCALE);
}

// round 12
// speedup vs baseline: 1.7504x; 1.0657x over previous
#include <cuda_runtime.h>
#include <cuda_fp16.h>
#include <math.h>
#include <stdint.h>

#define B_    2
#define S_    4096
#define HID_  2048
#define NH_   32
#define NKV_  8
#define HD_   64
#define ROWS_ (B_ * S_)          /* 8192 */
#define KVW_  (NKV_ * HD_)       /* 512  */

#define CTX_SCALE   (1.0f / 1024.0f)
#define CTX_UNSCALE 1024.0f

// weight offsets in the combined transposed-weight buffer (elements)
#define WQOFF 0
#define WKOFF (2048 * 2048)
#define WVOFF (WKOFF + 512 * 2048)
#define WPOFF (WVOFF + 512 * 2048)
#define WOOFF (WPOFF + 2048 * 2048)
#define WTOT  (WOOFF + 2048 * 2048)   /* 7168 * 2048 */

// ---------------- device scratch (no allocs allowed) ----------------
__device__ float g_q  [(size_t)ROWS_ * HID_];
__device__ float g_k  [(size_t)ROWS_ * KVW_];
__device__ float g_v  [(size_t)ROWS_ * KVW_];
__device__ float g_phi[(size_t)ROWS_ * HID_];
__device__ float g_qg [B_ * HID_];
__device__ float g_log[B_ * NH_ * S_];
__device__ float g_out[B_ * NH_ * HD_ * HD_];

__device__ __half g_xhi [(size_t)ROWS_ * HID_];
__device__ __half g_xlo [(size_t)ROWS_ * HID_];
__device__ __half g_whi [(size_t)WTOT];
__device__ __half g_wklo[(size_t)KVW_ * HID_];   // lo part for Wk only
__device__ __half g_phihi[(size_t)ROWS_ * HID_];
__device__ __half g_philo[(size_t)ROWS_ * HID_];

// ================= split-fp16 tensor-core GEMM =================
// 2-pass: C = (Ahi+Alo) @ Bhi^T * outScale      (exact A, fp16-quantized B)
//   3-stage cp.async pipeline, ONE __syncthreads per BK iter.
// 3-pass: C = (Ahi+Alo) @ (Bhi+Blo)^T           (exact A, ~fp32 B; for Wk)
// ropeFlag: apply RoPE+kappa in-register in the epilogue (Q/K projections).
//   Each warp's 64-col tile is one head; acc[mt][nt] / acc[mt][nt+4] hold
//   the (i, i+32) rotation pair for the same row.
// Block 128x128, BK=32, 8 warps (warp tile 32x64).

#define GPAD 40                 // smem row stride in fp16 elems (conflict-free)
#define SEC  (128 * GPAD)       // 5120 elems per component tile
#define STAGE2 (3 * SEC)        // Ahi, Alo, Bhi
#define SMEM2  (3 * STAGE2 * 2) /* 92160: 3 stages */
#define STAGE3 (4 * SEC)        // Ahi, Alo, Bhi, Blo
#define SMEM3  (2 * STAGE3 * 2) /* 81920: 2 stages */

__device__ __forceinline__ void cpasync16(unsigned smaddr, const void* g) {
    asm volatile("cp.async.cg.shared.global [%0], [%1], 16;" :: "r"(smaddr), "l"(g));
}

__device__ __forceinline__ unsigned smaddr_of(const void* p) {
    return (unsigned)__cvta_generic_to_shared(p);
}

#define MMA_FP16(c, a, b0, b1)                                              \
    asm volatile("mma.sync.aligned.m16n8k16.row.col.f32.f16.f16.f32 "       \
                 "{%0,%1,%2,%3}, {%4,%5,%6,%7}, {%8,%9}, {%0,%1,%2,%3};"    \
                 : "+f"(c[0]), "+f"(c[1]), "+f"(c[2]), "+f"(c[3])           \
                 : "r"(a[0]), "r"(a[1]), "r"(a[2]), "r"(a[3]),              \
                   "r"(b0), "r"(b1))

// In-register RoPE + kappa on the 2x8x4 accumulator tile. tg/g/wm as in GEMM.
#define ROPE_KAPPA_EPI(acc, yb, wm, g, tg)                                   \
    do {                                                                     \
        float inv_[8];                                                       \
        _Pragma("unroll")                                                    \
        for (int nt = 0; nt < 4; nt++)                                       \
            _Pragma("unroll")                                                \
            for (int j = 0; j < 2; j++)                                      \
                inv_[nt * 2 + j] =                                           \
                    expf((float)(nt * 8 + (tg) * 2 + j) * -0.28782313662425573f); \
        _Pragma("unroll")                                                    \
        for (int mt = 0; mt < 2; mt++)                                       \
            _Pragma("unroll")                                                \
            for (int rr = 0; rr < 2; rr++) {                                 \
                const int s_ = ((yb) + (wm) + mt * 16 + (g) + rr * 8) & (S_ - 1); \
                _Pragma("unroll")                                            \
                for (int nt = 0; nt < 4; nt++)                               \
                    _Pragma("unroll")                                        \
                    for (int j = 0; j < 2; j++) {                            \
                        float sn_, cs_;                                      \
                        sincosf((float)s_ * inv_[nt * 2 + j], &sn_, &cs_);   \
                        const int jj = rr * 2 + j;                           \
                        const float x1 = acc[mt][nt][jj];                    \
                        const float x2 = acc[mt][nt + 4][jj];                \
                        const float y1 = x1 * cs_ - x2 * sn_;                \
                        const float y2 = x2 * cs_ + x1 * sn_;                \
                        acc[mt][nt][jj]     = (y1 > 0.f) ? (y1 + 1.f) : expf(y1); \
                        acc[mt][nt + 4][jj] = (y2 > 0.f) ? (y2 + 1.f) : expf(y2); \
                    }                                                        \
            }                                                                \
    } while (0)

__device__ __forceinline__ void stage_load2(
    const __half* Ahi, const __half* Alo, const __half* Bhi,
    __half* sm, int tid, int K, int t)
{
#pragma unroll
    for (int i = 0; i < 2; i++) {
        const int idx = tid + i * 256;
        const int r   = idx >> 2;
        const int c8  = (idx & 3) * 8;
        const size_t goff = (size_t)r * K + (size_t)t * 32 + c8;
        const int soff = r * GPAD + c8;
        cpasync16(smaddr_of(sm + soff),           Ahi + goff);
        cpasync16(smaddr_of(sm + SEC + soff),     Alo + goff);
        cpasync16(smaddr_of(sm + 2 * SEC + soff), Bhi + goff);
    }
}

__global__ __launch_bounds__(256)
void fp16split_gemm(const __half* __restrict__ Ahi, const __half* __restrict__ Alo,
                    const __half* __restrict__ Bhi,
                    float* __restrict__ C, int M, int N, int K, float outScale,
                    int ropeFlag)
{
    extern __shared__ __half smem[];

    const int tid  = threadIdx.x;
    const int wid  = tid >> 5;
    const int lane = tid & 31;
    const int g    = lane >> 2;
    const int tg   = lane & 3;
    const int wm   = (wid >> 1) * 32;
    const int wn   = (wid & 1) * 64;

    const __half* A0 = Ahi + (size_t)(blockIdx.y * 128) * K;
    const __half* A1 = Alo + (size_t)(blockIdx.y * 128) * K;
    const __half* B0 = Bhi + (size_t)(blockIdx.x * 128) * K;

    float acc[2][8][4];
#pragma unroll
    for (int mt = 0; mt < 2; mt++)
#pragma unroll
        for (int nt = 0; nt < 8; nt++)
#pragma unroll
            for (int j = 0; j < 4; j++) acc[mt][nt][j] = 0.f;

    const int nT = K >> 5;

    stage_load2(A0, A1, B0, smem, tid, K, 0);
    asm volatile("cp.async.commit_group;");
    stage_load2(A0, A1, B0, smem + STAGE2, tid, K, 1);
    asm volatile("cp.async.commit_group;");

    int cur = 0;
    for (int t = 0; t < nT; t++) {
        if (t + 1 < nT) {
            asm volatile("cp.async.wait_group 1;");
        } else {
            asm volatile("cp.async.wait_group 0;");
        }
        __syncthreads();

        const uint32_t* sA0 = (const uint32_t*)(smem + cur * STAGE2);
        const uint32_t* sA1 = sA0 + SEC / 2;
        const uint32_t* sB0 = sA0 + SEC;

#pragma unroll
        for (int ks = 0; ks < 2; ks++) {
            uint32_t aH[2][4], aL[2][4];
#pragma unroll
            for (int mt = 0; mt < 2; mt++) {
                const int r0 = (wm + mt * 16 + g) * 20 + ks * 8 + tg;
                const int r1 = r0 + 8 * 20;
                aH[mt][0] = sA0[r0];     aH[mt][1] = sA0[r1];
                aH[mt][2] = sA0[r0 + 4]; aH[mt][3] = sA0[r1 + 4];
                aL[mt][0] = sA1[r0];     aL[mt][1] = sA1[r1];
                aL[mt][2] = sA1[r0 + 4]; aL[mt][3] = sA1[r1 + 4];
            }
#pragma unroll
            for (int nt = 0; nt < 8; nt++) {
                const int nb = (wn + nt * 8 + g) * 20 + ks * 8 + tg;
                const uint32_t bH0 = sB0[nb], bH1 = sB0[nb + 4];
#pragma unroll
                for (int mt = 0; mt < 2; mt++) {
                    MMA_FP16(acc[mt][nt], aH[mt], bH0, bH1);
                    MMA_FP16(acc[mt][nt], aL[mt], bH0, bH1);
                }
            }
        }

        if (t + 2 < nT) {
            const int nxt = (cur + 2 >= 3) ? cur - 1 : cur + 2;
            stage_load2(A0, A1, B0, smem + nxt * STAGE2, tid, K, t + 2);
            asm volatile("cp.async.commit_group;");
        }
        cur = (cur == 2) ? 0 : cur + 1;
    }

    if (ropeFlag) {
        const int yb = blockIdx.y * 128;
        ROPE_KAPPA_EPI(acc, yb, wm, g, tg);
    }

    float* Cb = C + (size_t)(blockIdx.y * 128 + wm) * N + blockIdx.x * 128 + wn;
#pragma unroll
    for (int mt = 0; mt < 2; mt++)
#pragma unroll
        for (int nt = 0; nt < 8; nt++) {
            const int col = nt * 8 + tg * 2;
            *(float2*)&Cb[(size_t)(mt * 16 + g) * N + col] = make_float2(
                acc[mt][nt][0] * outScale, acc[mt][nt][1] * outScale);
            *(float2*)&Cb[(size_t)(mt * 16 + g + 8) * N + col] = make_float2(
                acc[mt][nt][2] * outScale, acc[mt][nt][3] * outScale);
        }
}

// ---- 3-pass variant (B also split hi/lo) — used for the K projection ----
__device__ __forceinline__ void stage_load3(
    const __half* Ahi, const __half* Alo, const __half* Bhi, const __half* Blo,
    __half* sm, int tid, int K, int t)
{
#pragma unroll
    for (int i = 0; i < 2; i++) {
        const int idx = tid + i * 256;
        const int r   = idx >> 2;
        const int c8  = (idx & 3) * 8;
        const size_t goff = (size_t)r * K + (size_t)t * 32 + c8;
        const int soff = r * GPAD + c8;
        cpasync16(smaddr_of(sm + soff),           Ahi + goff);
        cpasync16(smaddr_of(sm + SEC + soff),     Alo + goff);
        cpasync16(smaddr_of(sm + 2 * SEC + soff), Bhi + goff);
        cpasync16(smaddr_of(sm + 3 * SEC + soff), Blo + goff);
    }
}

__global__ __launch_bounds__(256)
void fp16split3_gemm(const __half* __restrict__ Ahi, const __half* __restrict__ Alo,
                     const __half* __restrict__ Bhi, const __half* __restrict__ Blo,
                     float* __restrict__ C, int M, int N, int K, int ropeFlag)
{
    extern __shared__ __half smem[];

    const int tid  = threadIdx.x;
    const int wid  = tid >> 5;
    const int lane = tid & 31;
    const int g    = lane >> 2;
    const int tg   = lane & 3;
    const int wm   = (wid >> 1) * 32;
    const int wn   = (wid & 1) * 64;

    const __half* A0 = Ahi + (size_t)(blockIdx.y * 128) * K;
    const __half* A1 = Alo + (size_t)(blockIdx.y * 128) * K;
    const __half* B0 = Bhi + (size_t)(blockIdx.x * 128) * K;
    const __half* B1 = Blo + (size_t)(blockIdx.x * 128) * K;

    float acc[2][8][4];
#pragma unroll
    for (int mt = 0; mt < 2; mt++)
#pragma unroll
        for (int nt = 0; nt < 8; nt++)
#pragma unroll
            for (int j = 0; j < 4; j++) acc[mt][nt][j] = 0.f;

    stage_load3(A0, A1, B0, B1, smem, tid, K, 0);
    asm volatile("cp.async.commit_group;");

    const int nT = K >> 5;
    for (int t = 0; t < nT; t++) {
        if (t + 1 < nT) {
            stage_load3(A0, A1, B0, B1, smem + ((t + 1) & 1) * STAGE3, tid, K, t + 1);
            asm volatile("cp.async.commit_group;");
            asm volatile("cp.async.wait_group 1;");
        } else {
            asm volatile("cp.async.wait_group 0;");
        }
        __syncthreads();

        const uint32_t* sA0 = (const uint32_t*)(smem + (t & 1) * STAGE3);
        const uint32_t* sA1 = sA0 + SEC / 2;
        const uint32_t* sB0 = sA0 + SEC;
        const uint32_t* sB1 = sA0 + 3 * (SEC / 2);

#pragma unroll
        for (int ks = 0; ks < 2; ks++) {
            uint32_t aH[2][4], aL[2][4];
#pragma unroll
            for (int mt = 0; mt < 2; mt++) {
                const int r0 = (wm + mt * 16 + g) * 20 + ks * 8 + tg;
                const int r1 = r0 + 8 * 20;
                aH[mt][0] = sA0[r0];     aH[mt][1] = sA0[r1];
                aH[mt][2] = sA0[r0 + 4]; aH[mt][3] = sA0[r1 + 4];
                aL[mt][0] = sA1[r0];     aL[mt][1] = sA1[r1];
                aL[mt][2] = sA1[r0 + 4]; aL[mt][3] = sA1[r1 + 4];
            }
#pragma unroll
            for (int nt = 0; nt < 8; nt++) {
                const int nb = (wn + nt * 8 + g) * 20 + ks * 8 + tg;
                const uint32_t bH0 = sB0[nb], bH1 = sB0[nb + 4];
                const uint32_t bL0 = sB1[nb], bL1 = sB1[nb + 4];
#pragma unroll
                for (int mt = 0; mt < 2; mt++) {
                    MMA_FP16(acc[mt][nt], aH[mt], bH0, bH1);
                    MMA_FP16(acc[mt][nt], aH[mt], bL0, bL1);
                    MMA_FP16(acc[mt][nt], aL[mt], bH0, bH1);
                }
            }
        }
        __syncthreads();
    }

    if (ropeFlag) {
        const int yb = blockIdx.y * 128;
        ROPE_KAPPA_EPI(acc, yb, wm, g, tg);
    }

    float* Cb = C + (size_t)(blockIdx.y * 128 + wm) * N + blockIdx.x * 128 + wn;
#pragma unroll
    for (int mt = 0; mt < 2; mt++)
#pragma unroll
        for (int nt = 0; nt < 8; nt++) {
            const int col = nt * 8 + tg * 2;
            *(float2*)&Cb[(size_t)(mt * 16 + g) * N + col] =
                make_float2(acc[mt][nt][0], acc[mt][nt][1]);
            *(float2*)&Cb[(size_t)(mt * 16 + g + 8) * N + col] =
                make_float2(acc[mt][nt][2], acc[mt][nt][3]);
        }
}

// ---------------- fp32 -> (hi, lo) fp16 split ----------------
__global__ void cvt_split_kernel(const float* __restrict__ in,
                                 __half* __restrict__ hi,
                                 __half* __restrict__ lo, int n4)
{
    const int i = blockIdx.x * 256 + threadIdx.x;
    if (i >= n4) return;
    const float4 x = ((const float4*)in)[i];
    union { __half b[4]; uint2 u; } H, L;
    float v[4] = {x.x, x.y, x.z, x.w};
#pragma unroll
    for (int j = 0; j < 4; j++) {
        const __half h = __float2half_rn(v[j]);
        H.b[j] = h;
        L.b[j] = __float2half_rn(v[j] - __half2float(h));
    }
    ((uint2*)hi)[i] = H.u;
    ((uint2*)lo)[i] = L.u;
}

// ---------------- weight transpose: fp32 [K][N] -> fp16 [N][K] ----------------
__global__ void wtrans_kernel(const float* __restrict__ W,
                              __half* __restrict__ Whi, int K, int N)
{
    __shared__ float tile[32][33];
    const int n0 = blockIdx.x * 32, k0 = blockIdx.y * 32;
    const int tx = threadIdx.x & 31, ty = threadIdx.x >> 5;
#pragma unroll
    for (int i = 0; i < 32; i += 8)
        tile[ty + i][tx] = W[(size_t)(k0 + ty + i) * N + n0 + tx];
    __syncthreads();
#pragma unroll
    for (int i = 0; i < 32; i += 8)
        Whi[(size_t)(n0 + ty + i) * K + k0 + tx] = __float2half_rn(tile[tx][ty + i]);
}

__global__ void wtrans2_kernel(const float* __restrict__ W,
                               __half* __restrict__ Whi,
                               __half* __restrict__ Wlo, int K, int N)
{
    __shared__ float tile[32][33];
    const int n0 = blockIdx.x * 32, k0 = blockIdx.y * 32;
    const int tx = threadIdx.x & 31, ty = threadIdx.x >> 5;
#pragma unroll
    for (int i = 0; i < 32; i += 8)
        tile[ty + i][tx] = W[(size_t)(k0 + ty + i) * N + n0 + tx];
    __syncthreads();
#pragma unroll
    for (int i = 0; i < 32; i += 8) {
        const float v = tile[tx][ty + i];
        const __half h = __float2half_rn(v);
        const size_t o = (size_t)(n0 + ty + i) * K + k0 + tx;
        Whi[o] = h;
        Wlo[o] = __float2half_rn(v - __half2float(h));
    }
}

// ---------------- zero accumulators (g_out + g_qg) ----------------
__global__ void zero_acc_kernel()
{
    const int i = blockIdx.x * 256 + threadIdx.x;
    if (i < B_ * NH_ * HD_ * HD_) g_out[i] = 0.f;
    if (i < B_ * HID_)            g_qg[i]  = 0.f;
}

__global__ void qg_partial_kernel()  // grid (HID_/256, S_/256, B_)
{
    const int col = blockIdx.x * 256 + threadIdx.x;
    const int b   = blockIdx.z;
    const int r0  = blockIdx.y * 256;
    const float* base = g_q + ((size_t)(b * S_ + r0)) * HID_ + col;
    float s = 0.f;
#pragma unroll 8
    for (int r = 0; r < 256; r++) s += base[(size_t)r * HID_];
    atomicAdd(&g_qg[b * HID_ + col], s);
}

// ---------------- logits ----------------
__global__ void logits_kernel()      // <<<256,256>>>
{
    const int gt   = blockIdx.x * blockDim.x + threadIdx.x;
    const int warp = gt >> 5;
    const int lane = gt & 31;
    const int chunk = warp & 31;
    const int bh    = warp >> 5;
    const int h = bh & 31, b = bh >> 5;
    const int kv = h >> 2;

    float2 qv = *(const float2*)&g_qg[b * HID_ + h * 64 + lane * 2];
    const float sc = 1.0f / (float)S_;
    qv.x *= sc; qv.y *= sc;

    const float* kb = g_k + (size_t)b * S_ * KVW_ + kv * 64 + lane * 2;
    float* lb = g_log + (size_t)bh * S_;
    const int s0 = chunk * 128;
    for (int s = s0; s < s0 + 128; s++) {
        const float2 k2 = *(const float2*)(kb + (size_t)s * KVW_);
        float d = k2.x * qv.x + k2.y * qv.y;
#pragma unroll
        for (int o = 16; o > 0; o >>= 1) d += __shfl_xor_sync(0xffffffffu, d, o);
        if (lane == 0) lb[s] = d;
    }
}

// ---------------- softmax over S per (b,h), scaled by S, in place ----------------
__global__ __launch_bounds__(256)
void softmax_kernel()                // <<<64,256>>>
{
    __shared__ float buf[S_];
    __shared__ float red[256];
    float* row = g_log + (size_t)blockIdx.x * S_;
    const int t = threadIdx.x;

    float m = -1e30f;
    for (int i = t; i < S_; i += 256) { const float v = row[i]; buf[i] = v; m = fmaxf(m, v); }
    red[t] = m; __syncthreads();
    for (int st = 128; st > 0; st >>= 1) { if (t < st) red[t] = fmaxf(red[t], red[t + st]); __syncthreads(); }
    m = red[0]; __syncthreads();

    float sum = 0.f;
    for (int i = t; i < S_; i += 256) { const float e = expf(buf[i] - m); buf[i] = e; sum += e; }
    red[t] = sum; __syncthreads();
    for (int st = 128; st > 0; st >>= 1) { if (t < st) red[t] += red[t + st]; __syncthreads(); }
    const float inv = (float)S_ / red[0];
    for (int i = t; i < S_; i += 256) row[i] = buf[i] * inv;
}

// ---------------- state[b,h] (64x64), split 4 ways over S, atomic merge --------
__global__ __launch_bounds__(256)
void outer_kernel()                  // grid (4, 64)
{
    const int bh = blockIdx.y;
    const int h = bh & 31, b = bh >> 5;
    const int kv = h >> 2;
    __shared__ float ks[32][64];
    __shared__ float vs[32][64];
    const int t = threadIdx.x;
    const int ti = t >> 4, tj = t & 15;
    float acc[4][4] = {};

    const float* kb = g_k + (size_t)b * S_ * KVW_ + kv * 64;
    const float* vb = g_v + (size_t)b * S_ * KVW_ + kv * 64;
    const float* ab = g_log + (size_t)bh * S_;

    const int sBeg = blockIdx.x * (S_ / 4);
    const int sEnd = sBeg + (S_ / 4);
    for (int s0 = sBeg; s0 < sEnd; s0 += 32) {
#pragma unroll
        for (int rep = 0; rep < 2; rep++) {
            const int idx = t + rep * 256;
            const int r = idx >> 4;
            const int c = (idx & 15) << 2;
            const float a = ab[s0 + r];
            const float4 k4 = *(const float4*)(kb + (size_t)(s0 + r) * KVW_ + c);
            *(float4*)&ks[r][c] = make_float4(k4.x * a, k4.y * a, k4.z * a, k4.w * a);
            *(float4*)&vs[r][c] = *(const float4*)(vb + (size_t)(s0 + r) * KVW_ + c);
        }
        __syncthreads();
#pragma unroll
        for (int ss = 0; ss < 32; ss++) {
            float ka[4], vf[4];
            *(float4*)ka = *(const float4*)&ks[ss][ti * 4];
            *(float4*)vf = *(const float4*)&vs[ss][tj * 4];
#pragma unroll
            for (int i = 0; i < 4; i++)
#pragma unroll
                for (int j = 0; j < 4; j++)
                    acc[i][j] = fmaf(ka[i], vf[j], acc[i][j]);
        }
        __syncthreads();
    }
#pragma unroll
    for (int i = 0; i < 4; i++)
#pragma unroll
        for (int j = 0; j < 4; j++)
            atomicAdd(&g_out[(size_t)bh * 4096 + (size_t)(ti * 4 + i) * 64 + tj * 4 + j],
                      acc[i][j]);
}

// ---------------- ctx = phi * (Qk @ state) * CTX_SCALE -> split fp16 ----------------
__global__ __launch_bounds__(256)
void ctx_kernel()                    // grid (S_/64, NH_, B_)
{
    const int b = blockIdx.z, h = blockIdx.y, s0 = blockIdx.x * 64;
    __shared__ float Os[64][64];
    __shared__ float Qs[64][68];
    const int t = threadIdx.x;

    const float* ob = g_out + (size_t)(b * NH_ + h) * 4096;
#pragma unroll
    for (int rep = 0; rep < 4; rep++)
        ((float4*)&Os[0][0])[t + rep * 256] = ((const float4*)ob)[t + rep * 256];

    const float* qb = g_q + ((size_t)(b * S_ + s0)) * HID_ + h * 64;
#pragma unroll
    for (int rep = 0; rep < 4; rep++) {
        const int idx = t + rep * 256;
        const int r = idx >> 4;
        const int c = (idx & 15) << 2;
        *(float4*)&Qs[r][c] = *(const float4*)(qb + (size_t)r * HID_ + c);
    }
    __syncthreads();

    const int ti = t >> 4, tj = t & 15;
    float acc[4][4] = {};
#pragma unroll 4
    for (int d = 0; d < 64; d++) {
        float o[4];
        *(float4*)o = *(const float4*)&Os[d][tj * 4];
#pragma unroll
        for (int i = 0; i < 4; i++) {
            const float qv = Qs[ti * 4 + i][d];
#pragma unroll
            for (int j = 0; j < 4; j++)
                acc[i][j] = fmaf(qv, o[j], acc[i][j]);
        }
    }

    const float* pb = g_phi + ((size_t)(b * S_ + s0)) * HID_ + h * 64;
    __half* ph = g_phihi + ((size_t)(b * S_ + s0)) * HID_ + h * 64;
    __half* pl = g_philo + ((size_t)(b * S_ + s0)) * HID_ + h * 64;
#pragma unroll
    for (int i = 0; i < 4; i++) {
        const size_t off = (size_t)(ti * 4 + i) * HID_ + tj * 4;
        const float4 p = *(const float4*)(pb + off);
        float r[4] = {p.x * acc[i][0] * CTX_SCALE, p.y * acc[i][1] * CTX_SCALE,
                      p.z * acc[i][2] * CTX_SCALE, p.w * acc[i][3] * CTX_SCALE};
        union { __half b[4]; uint2 u; } H, L;
#pragma unroll
        for (int j = 0; j < 4; j++) {
            const __half hh = __float2half_rn(r[j]);
            H.b[j] = hh;
            L.b[j] = __float2half_rn(r[j] - __half2float(hh));
        }
        *(uint2*)(ph + off) = H.u;
        *(uint2*)(pl + off) = L.u;
    }
}

// ---------------- launch ----------------
extern "C" void kernel_launch(void* const* d_in, const int* in_sizes, int n_in,
                              void* d_out, int out_size)
{
    const float* X   = (const float*)d_in[0];
    const float* Wq  = (const float*)d_in[1];
    const float* Wk  = (const float*)d_in[2];
    const float* Wv  = (const float*)d_in[3];
    const float* Wph = (const float*)d_in[4];
    const float* Wo  = (const float*)d_in[5];
    float* out = (float*)d_out;

    float *q, *k, *v, *ph;
    __half *xhi, *xlo, *whi, *wklo, *phihi, *philo;
    cudaGetSymbolAddress((void**)&q,     g_q);
    cudaGetSymbolAddress((void**)&k,     g_k);
    cudaGetSymbolAddress((void**)&v,     g_v);
    cudaGetSymbolAddress((void**)&ph,    g_phi);
    cudaGetSymbolAddress((void**)&xhi,   g_xhi);
    cudaGetSymbolAddress((void**)&xlo,   g_xlo);
    cudaGetSymbolAddress((void**)&whi,   g_whi);
    cudaGetSymbolAddress((void**)&wklo,  g_wklo);
    cudaGetSymbolAddress((void**)&phihi, g_phihi);
    cudaGetSymbolAddress((void**)&philo, g_philo);

    cudaFuncSetAttribute(fp16split_gemm,
                         cudaFuncAttributeMaxDynamicSharedMemorySize, SMEM2);
    cudaFuncSetAttribute(fp16split3_gemm,
                         cudaFuncAttributeMaxDynamicSharedMemorySize, SMEM3);

    // Launches 1-5: conversions (Wo's transpose deferred so launch #6 = Q GEMM
    // and the ncu capture window lands on the GEMM, not a wtrans).
    cvt_split_kernel<<<(ROWS_ * HID_ / 4 + 255) / 256, 256>>>(X, xhi, xlo, ROWS_ * HID_ / 4);
    wtrans_kernel <<<dim3(HID_ / 32, HID_ / 32), 256>>>(Wq,  whi + WQOFF, HID_, HID_);
    wtrans2_kernel<<<dim3(KVW_ / 32, HID_ / 32), 256>>>(Wk,  whi + WKOFF, wklo, HID_, KVW_);
    wtrans_kernel <<<dim3(KVW_ / 32, HID_ / 32), 256>>>(Wv,  whi + WVOFF, HID_, KVW_);
    wtrans_kernel <<<dim3(HID_ / 32, HID_ / 32), 256>>>(Wph, whi + WPOFF, HID_, HID_);

    // Projections. RoPE+kappa fused into Q/K epilogues.
    fp16split_gemm<<<dim3(HID_ / 128, ROWS_ / 128), 256, SMEM2>>>(
        xhi, xlo, whi + WQOFF, q,  ROWS_, HID_, HID_, 1.0f, 1);
    fp16split3_gemm<<<dim3(KVW_ / 128, ROWS_ / 128), 256, SMEM3>>>(
        xhi, xlo, whi + WKOFF, wklo, k, ROWS_, KVW_, HID_, 1);
    fp16split_gemm<<<dim3(KVW_ / 128, ROWS_ / 128), 256, SMEM2>>>(
        xhi, xlo, whi + WVOFF, v,  ROWS_, KVW_, HID_, 1.0f, 0);
    fp16split_gemm<<<dim3(HID_ / 128, ROWS_ / 128), 256, SMEM2>>>(
        xhi, xlo, whi + WPOFF, ph, ROWS_, HID_, HID_, 1.0f, 0);

    wtrans_kernel <<<dim3(HID_ / 32, HID_ / 32), 256>>>(Wo,  whi + WOOFF, HID_, HID_);

    // Zero accumulators, then Qg column sums (1/S folded into logits)
    zero_acc_kernel<<<(B_ * NH_ * HD_ * HD_ + 255) / 256, 256>>>();
    qg_partial_kernel<<<dim3(HID_ / 256, S_ / 256, B_), 256>>>();

    // logits -> alpha -> state
    logits_kernel<<<256, 256>>>();
    softmax_kernel<<<B_ * NH_, 256>>>();
    outer_kernel<<<dim3(4, B_ * NH_), 256>>>();

    // ctx = phi*(Qk@state)*2^-10 -> split fp16, then Wo GEMM rescales by 2^10
    ctx_kernel<<<dim3(S_ / 64, NH_, B_), 256>>>();
    fp16split_gemm<<<dim3(HID_ / 128, ROWS_ / 128), 256, SMEM2>>>(
        phihi, philo, whi + WOOFF, out, ROWS_, HID_, HID_, CTX_UNSCALE, 0);
}

// round 14
// speedup vs baseline: 2.1426x; 1.2241x over previous
#include <cuda_runtime.h>
#include <cuda_fp16.h>
#include <math.h>
#include <stdint.h>

#define B_    2
#define S_    4096
#define HID_  2048
#define NH_   32
#define NKV_  8
#define HD_   64
#define ROWS_ (B_ * S_)          /* 8192 */
#define KVW_  (NKV_ * HD_)       /* 512  */

#define CTX_SCALE   (1.0f / 1024.0f)
#define CTX_UNSCALE 1024.0f

// weight offsets in the combined transposed-weight buffer (elements)
#define WQOFF 0
#define WKOFF (2048 * 2048)
#define WVOFF (WKOFF + 512 * 2048)
#define WPOFF (WVOFF + 512 * 2048)
#define WOOFF (WPOFF + 2048 * 2048)
#define WTOT  (WOOFF + 2048 * 2048)   /* 7168 * 2048 */

// ---------------- device scratch (no allocs allowed) ----------------
__device__ float g_q  [(size_t)ROWS_ * HID_];
__device__ float g_k  [(size_t)ROWS_ * KVW_];
__device__ float g_v  [(size_t)ROWS_ * KVW_];
__device__ float g_phi[(size_t)ROWS_ * HID_];
__device__ float g_qg [B_ * HID_];
__device__ float g_log[B_ * NH_ * S_];
__device__ float g_out[B_ * NH_ * HD_ * HD_];

__device__ __half g_xhi [(size_t)ROWS_ * HID_];
__device__ __half g_xlo [(size_t)ROWS_ * HID_];
__device__ __half g_whi [(size_t)WTOT];
__device__ __half g_wklo[(size_t)KVW_ * HID_];   // lo part for Wk only
__device__ __half g_phihi[(size_t)ROWS_ * HID_];

// ================= split-fp16 tensor-core GEMM =================
// 1-pass: C = Ahi @ Bhi^T * outScale            (fp16 A and B; phi / Wo paths)
// 2-pass: C = (Ahi+Alo) @ Bhi^T * outScale      (exact A, fp16-quantized B)
// 3-pass: C = (Ahi+Alo) @ (Bhi+Blo)^T           (exact A, ~fp32 B; for Wk)
// ropeFlag: apply RoPE+kappa in-register in the epilogue (Q/K projections).
// Block 128x128, BK=32, 8 warps (warp tile 32x64), 3-stage cp.async pipeline
// (2-stage for the 3-pass K path).

#define GPAD 40                 // smem row stride in fp16 elems (conflict-free)
#define SEC  (128 * GPAD)       // 5120 elems per component tile
#define STAGE1 (2 * SEC)        // Ahi, Bhi
#define SMEM1  (3 * STAGE1 * 2) /* 61440: 3 stages */
#define STAGE2 (3 * SEC)        // Ahi, Alo, Bhi
#define SMEM2  (3 * STAGE2 * 2) /* 92160: 3 stages */
#define STAGE3 (4 * SEC)        // Ahi, Alo, Bhi, Blo
#define SMEM3  (2 * STAGE3 * 2) /* 81920: 2 stages */

__device__ __forceinline__ void cpasync16(unsigned smaddr, const void* g) {
    asm volatile("cp.async.cg.shared.global [%0], [%1], 16;" :: "r"(smaddr), "l"(g));
}

__device__ __forceinline__ unsigned smaddr_of(const void* p) {
    return (unsigned)__cvta_generic_to_shared(p);
}

#define MMA_FP16(c, a, b0, b1)                                              \
    asm volatile("mma.sync.aligned.m16n8k16.row.col.f32.f16.f16.f32 "       \
                 "{%0,%1,%2,%3}, {%4,%5,%6,%7}, {%8,%9}, {%0,%1,%2,%3};"    \
                 : "+f"(c[0]), "+f"(c[1]), "+f"(c[2]), "+f"(c[3])           \
                 : "r"(a[0]), "r"(a[1]), "r"(a[2]), "r"(a[3]),              \
                   "r"(b0), "r"(b1))

// In-register RoPE + kappa on the 2x8x4 accumulator tile. tg/g/wm as in GEMM.
#define ROPE_KAPPA_EPI(acc, yb, wm, g, tg)                                   \
    do {                                                                     \
        float inv_[8];                                                       \
        _Pragma("unroll")                                                    \
        for (int nt = 0; nt < 4; nt++)                                       \
            _Pragma("unroll")                                                \
            for (int j = 0; j < 2; j++)                                      \
                inv_[nt * 2 + j] =                                           \
                    expf((float)(nt * 8 + (tg) * 2 + j) * -0.28782313662425573f); \
        _Pragma("unroll")                                                    \
        for (int mt = 0; mt < 2; mt++)                                       \
            _Pragma("unroll")                                                \
            for (int rr = 0; rr < 2; rr++) {                                 \
                const int s_ = ((yb) + (wm) + mt * 16 + (g) + rr * 8) & (S_ - 1); \
                _Pragma("unroll")                                            \
                for (int nt = 0; nt < 4; nt++)                               \
                    _Pragma("unroll")                                        \
                    for (int j = 0; j < 2; j++) {                            \
                        float sn_, cs_;                                      \
                        sincosf((float)s_ * inv_[nt * 2 + j], &sn_, &cs_);   \
                        const int jj = rr * 2 + j;                           \
                        const float x1 = acc[mt][nt][jj];                    \
                        const float x2 = acc[mt][nt + 4][jj];                \
                        const float y1 = x1 * cs_ - x2 * sn_;                \
                        const float y2 = x2 * cs_ + x1 * sn_;                \
                        acc[mt][nt][jj]     = (y1 > 0.f) ? (y1 + 1.f) : expf(y1); \
                        acc[mt][nt + 4][jj] = (y2 > 0.f) ? (y2 + 1.f) : expf(y2); \
                    }                                                        \
            }                                                                \
    } while (0)

// ---------------- 1-pass GEMM (phi, Wo) ----------------
__device__ __forceinline__ void stage_load1(
    const __half* Ahi, const __half* Bhi,
    __half* sm, int tid, int K, int t)
{
#pragma unroll
    for (int i = 0; i < 2; i++) {
        const int idx = tid + i * 256;
        const int r   = idx >> 2;
        const int c8  = (idx & 3) * 8;
        const size_t goff = (size_t)r * K + (size_t)t * 32 + c8;
        const int soff = r * GPAD + c8;
        cpasync16(smaddr_of(sm + soff),       Ahi + goff);
        cpasync16(smaddr_of(sm + SEC + soff), Bhi + goff);
    }
}

__global__ __launch_bounds__(256)
void fp16_1pass_gemm(const __half* __restrict__ Ahi, const __half* __restrict__ Bhi,
                     float* __restrict__ C, int M, int N, int K, float outScale)
{
    extern __shared__ __half smem[];

    const int tid  = threadIdx.x;
    const int wid  = tid >> 5;
    const int lane = tid & 31;
    const int g    = lane >> 2;
    const int tg   = lane & 3;
    const int wm   = (wid >> 1) * 32;
    const int wn   = (wid & 1) * 64;

    const __half* A0 = Ahi + (size_t)(blockIdx.y * 128) * K;
    const __half* B0 = Bhi + (size_t)(blockIdx.x * 128) * K;

    float acc[2][8][4];
#pragma unroll
    for (int mt = 0; mt < 2; mt++)
#pragma unroll
        for (int nt = 0; nt < 8; nt++)
#pragma unroll
            for (int j = 0; j < 4; j++) acc[mt][nt][j] = 0.f;

    const int nT = K >> 5;

    stage_load1(A0, B0, smem, tid, K, 0);
    asm volatile("cp.async.commit_group;");
    stage_load1(A0, B0, smem + STAGE1, tid, K, 1);
    asm volatile("cp.async.commit_group;");

    int cur = 0;
    for (int t = 0; t < nT; t++) {
        if (t + 1 < nT) {
            asm volatile("cp.async.wait_group 1;");
        } else {
            asm volatile("cp.async.wait_group 0;");
        }
        __syncthreads();

        const uint32_t* sA0 = (const uint32_t*)(smem + cur * STAGE1);
        const uint32_t* sB0 = sA0 + SEC / 2;

#pragma unroll
        for (int ks = 0; ks < 2; ks++) {
            uint32_t aH[2][4];
#pragma unroll
            for (int mt = 0; mt < 2; mt++) {
                const int r0 = (wm + mt * 16 + g) * 20 + ks * 8 + tg;
                const int r1 = r0 + 8 * 20;
                aH[mt][0] = sA0[r0];     aH[mt][1] = sA0[r1];
                aH[mt][2] = sA0[r0 + 4]; aH[mt][3] = sA0[r1 + 4];
            }
#pragma unroll
            for (int nt = 0; nt < 8; nt++) {
                const int nb = (wn + nt * 8 + g) * 20 + ks * 8 + tg;
                const uint32_t bH0 = sB0[nb], bH1 = sB0[nb + 4];
#pragma unroll
                for (int mt = 0; mt < 2; mt++)
                    MMA_FP16(acc[mt][nt], aH[mt], bH0, bH1);
            }
        }

        if (t + 2 < nT) {
            const int nxt = (cur + 2 >= 3) ? cur - 1 : cur + 2;
            stage_load1(A0, B0, smem + nxt * STAGE1, tid, K, t + 2);
            asm volatile("cp.async.commit_group;");
        }
        cur = (cur == 2) ? 0 : cur + 1;
    }

    float* Cb = C + (size_t)(blockIdx.y * 128 + wm) * N + blockIdx.x * 128 + wn;
#pragma unroll
    for (int mt = 0; mt < 2; mt++)
#pragma unroll
        for (int nt = 0; nt < 8; nt++) {
            const int col = nt * 8 + tg * 2;
            *(float2*)&Cb[(size_t)(mt * 16 + g) * N + col] = make_float2(
                acc[mt][nt][0] * outScale, acc[mt][nt][1] * outScale);
            *(float2*)&Cb[(size_t)(mt * 16 + g + 8) * N + col] = make_float2(
                acc[mt][nt][2] * outScale, acc[mt][nt][3] * outScale);
        }
}

// ---------------- 2-pass GEMM (Q, V) ----------------
__device__ __forceinline__ void stage_load2(
    const __half* Ahi, const __half* Alo, const __half* Bhi,
    __half* sm, int tid, int K, int t)
{
#pragma unroll
    for (int i = 0; i < 2; i++) {
        const int idx = tid + i * 256;
        const int r   = idx >> 2;
        const int c8  = (idx & 3) * 8;
        const size_t goff = (size_t)r * K + (size_t)t * 32 + c8;
        const int soff = r * GPAD + c8;
        cpasync16(smaddr_of(sm + soff),           Ahi + goff);
        cpasync16(smaddr_of(sm + SEC + soff),     Alo + goff);
        cpasync16(smaddr_of(sm + 2 * SEC + soff), Bhi + goff);
    }
}

__global__ __launch_bounds__(256)
void fp16split_gemm(const __half* __restrict__ Ahi, const __half* __restrict__ Alo,
                    const __half* __restrict__ Bhi,
                    float* __restrict__ C, int M, int N, int K, float outScale,
                    int ropeFlag)
{
    extern __shared__ __half smem[];

    const int tid  = threadIdx.x;
    const int wid  = tid >> 5;
    const int lane = tid & 31;
    const int g    = lane >> 2;
    const int tg   = lane & 3;
    const int wm   = (wid >> 1) * 32;
    const int wn   = (wid & 1) * 64;

    const __half* A0 = Ahi + (size_t)(blockIdx.y * 128) * K;
    const __half* A1 = Alo + (size_t)(blockIdx.y * 128) * K;
    const __half* B0 = Bhi + (size_t)(blockIdx.x * 128) * K;

    float acc[2][8][4];
#pragma unroll
    for (int mt = 0; mt < 2; mt++)
#pragma unroll
        for (int nt = 0; nt < 8; nt++)
#pragma unroll
            for (int j = 0; j < 4; j++) acc[mt][nt][j] = 0.f;

    const int nT = K >> 5;

    stage_load2(A0, A1, B0, smem, tid, K, 0);
    asm volatile("cp.async.commit_group;");
    stage_load2(A0, A1, B0, smem + STAGE2, tid, K, 1);
    asm volatile("cp.async.commit_group;");

    int cur = 0;
    for (int t = 0; t < nT; t++) {
        if (t + 1 < nT) {
            asm volatile("cp.async.wait_group 1;");
        } else {
            asm volatile("cp.async.wait_group 0;");
        }
        __syncthreads();

        const uint32_t* sA0 = (const uint32_t*)(smem + cur * STAGE2);
        const uint32_t* sA1 = sA0 + SEC / 2;
        const uint32_t* sB0 = sA0 + SEC;

#pragma unroll
        for (int ks = 0; ks < 2; ks++) {
            uint32_t aH[2][4], aL[2][4];
#pragma unroll
            for (int mt = 0; mt < 2; mt++) {
                const int r0 = (wm + mt * 16 + g) * 20 + ks * 8 + tg;
                const int r1 = r0 + 8 * 20;
                aH[mt][0] = sA0[r0];     aH[mt][1] = sA0[r1];
                aH[mt][2] = sA0[r0 + 4]; aH[mt][3] = sA0[r1 + 4];
                aL[mt][0] = sA1[r0];     aL[mt][1] = sA1[r1];
                aL[mt][2] = sA1[r0 + 4]; aL[mt][3] = sA1[r1 + 4];
            }
#pragma unroll
            for (int nt = 0; nt < 8; nt++) {
                const int nb = (wn + nt * 8 + g) * 20 + ks * 8 + tg;
                const uint32_t bH0 = sB0[nb], bH1 = sB0[nb + 4];
#pragma unroll
                for (int mt = 0; mt < 2; mt++) {
                    MMA_FP16(acc[mt][nt], aH[mt], bH0, bH1);
                    MMA_FP16(acc[mt][nt], aL[mt], bH0, bH1);
                }
            }
        }

        if (t + 2 < nT) {
            const int nxt = (cur + 2 >= 3) ? cur - 1 : cur + 2;
            stage_load2(A0, A1, B0, smem + nxt * STAGE2, tid, K, t + 2);
            asm volatile("cp.async.commit_group;");
        }
        cur = (cur == 2) ? 0 : cur + 1;
    }

    if (ropeFlag) {
        const int yb = blockIdx.y * 128;
        ROPE_KAPPA_EPI(acc, yb, wm, g, tg);
    }

    float* Cb = C + (size_t)(blockIdx.y * 128 + wm) * N + blockIdx.x * 128 + wn;
#pragma unroll
    for (int mt = 0; mt < 2; mt++)
#pragma unroll
        for (int nt = 0; nt < 8; nt++) {
            const int col = nt * 8 + tg * 2;
            *(float2*)&Cb[(size_t)(mt * 16 + g) * N + col] = make_float2(
                acc[mt][nt][0] * outScale, acc[mt][nt][1] * outScale);
            *(float2*)&Cb[(size_t)(mt * 16 + g + 8) * N + col] = make_float2(
                acc[mt][nt][2] * outScale, acc[mt][nt][3] * outScale);
        }
}

// ---- 3-pass variant (B also split hi/lo) — used for the K projection ----
__device__ __forceinline__ void stage_load3(
    const __half* Ahi, const __half* Alo, const __half* Bhi, const __half* Blo,
    __half* sm, int tid, int K, int t)
{
#pragma unroll
    for (int i = 0; i < 2; i++) {
        const int idx = tid + i * 256;
        const int r   = idx >> 2;
        const int c8  = (idx & 3) * 8;
        const size_t goff = (size_t)r * K + (size_t)t * 32 + c8;
        const int soff = r * GPAD + c8;
        cpasync16(smaddr_of(sm + soff),           Ahi + goff);
        cpasync16(smaddr_of(sm + SEC + soff),     Alo + goff);
        cpasync16(smaddr_of(sm + 2 * SEC + soff), Bhi + goff);
        cpasync16(smaddr_of(sm + 3 * SEC + soff), Blo + goff);
    }
}

__global__ __launch_bounds__(256)
void fp16split3_gemm(const __half* __restrict__ Ahi, const __half* __restrict__ Alo,
                     const __half* __restrict__ Bhi, const __half* __restrict__ Blo,
                     float* __restrict__ C, int M, int N, int K, int ropeFlag)
{
    extern __shared__ __half smem[];

    const int tid  = threadIdx.x;
    const int wid  = tid >> 5;
    const int lane = tid & 31;
    const int g    = lane >> 2;
    const int tg   = lane & 3;
    const int wm   = (wid >> 1) * 32;
    const int wn   = (wid & 1) * 64;

    const __half* A0 = Ahi + (size_t)(blockIdx.y * 128) * K;
    const __half* A1 = Alo + (size_t)(blockIdx.y * 128) * K;
    const __half* B0 = Bhi + (size_t)(blockIdx.x * 128) * K;
    const __half* B1 = Blo + (size_t)(blockIdx.x * 128) * K;

    float acc[2][8][4];
#pragma unroll
    for (int mt = 0; mt < 2; mt++)
#pragma unroll
        for (int nt = 0; nt < 8; nt++)
#pragma unroll
            for (int j = 0; j < 4; j++) acc[mt][nt][j] = 0.f;

    stage_load3(A0, A1, B0, B1, smem, tid, K, 0);
    asm volatile("cp.async.commit_group;");

    const int nT = K >> 5;
    for (int t = 0; t < nT; t++) {
        if (t + 1 < nT) {
            stage_load3(A0, A1, B0, B1, smem + ((t + 1) & 1) * STAGE3, tid, K, t + 1);
            asm volatile("cp.async.commit_group;");
            asm volatile("cp.async.wait_group 1;");
        } else {
            asm volatile("cp.async.wait_group 0;");
        }
        __syncthreads();

        const uint32_t* sA0 = (const uint32_t*)(smem + (t & 1) * STAGE3);
        const uint32_t* sA1 = sA0 + SEC / 2;
        const uint32_t* sB0 = sA0 + SEC;
        const uint32_t* sB1 = sA0 + 3 * (SEC / 2);

#pragma unroll
        for (int ks = 0; ks < 2; ks++) {
            uint32_t aH[2][4], aL[2][4];
#pragma unroll
            for (int mt = 0; mt < 2; mt++) {
                const int r0 = (wm + mt * 16 + g) * 20 + ks * 8 + tg;
                const int r1 = r0 + 8 * 20;
                aH[mt][0] = sA0[r0];     aH[mt][1] = sA0[r1];
                aH[mt][2] = sA0[r0 + 4]; aH[mt][3] = sA0[r1 + 4];
                aL[mt][0] = sA1[r0];     aL[mt][1] = sA1[r1];
                aL[mt][2] = sA1[r0 + 4]; aL[mt][3] = sA1[r1 + 4];
            }
#pragma unroll
            for (int nt = 0; nt < 8; nt++) {
                const int nb = (wn + nt * 8 + g) * 20 + ks * 8 + tg;
                const uint32_t bH0 = sB0[nb], bH1 = sB0[nb + 4];
                const uint32_t bL0 = sB1[nb], bL1 = sB1[nb + 4];
#pragma unroll
                for (int mt = 0; mt < 2; mt++) {
                    MMA_FP16(acc[mt][nt], aH[mt], bH0, bH1);
                    MMA_FP16(acc[mt][nt], aH[mt], bL0, bL1);
                    MMA_FP16(acc[mt][nt], aL[mt], bH0, bH1);
                }
            }
        }
        __syncthreads();
    }

    if (ropeFlag) {
        const int yb = blockIdx.y * 128;
        ROPE_KAPPA_EPI(acc, yb, wm, g, tg);
    }

    float* Cb = C + (size_t)(blockIdx.y * 128 + wm) * N + blockIdx.x * 128 + wn;
#pragma unroll
    for (int mt = 0; mt < 2; mt++)
#pragma unroll
        for (int nt = 0; nt < 8; nt++) {
            const int col = nt * 8 + tg * 2;
            *(float2*)&Cb[(size_t)(mt * 16 + g) * N + col] =
                make_float2(acc[mt][nt][0], acc[mt][nt][1]);
            *(float2*)&Cb[(size_t)(mt * 16 + g + 8) * N + col] =
                make_float2(acc[mt][nt][2], acc[mt][nt][3]);
        }
}

// ---------------- fp32 -> (hi, lo) fp16 split ----------------
__global__ void cvt_split_kernel(const float* __restrict__ in,
                                 __half* __restrict__ hi,
                                 __half* __restrict__ lo, int n4)
{
    const int i = blockIdx.x * 256 + threadIdx.x;
    if (i >= n4) return;
    const float4 x = ((const float4*)in)[i];
    union { __half b[4]; uint2 u; } H, L;
    float v[4] = {x.x, x.y, x.z, x.w};
#pragma unroll
    for (int j = 0; j < 4; j++) {
        const __half h = __float2half_rn(v[j]);
        H.b[j] = h;
        L.b[j] = __float2half_rn(v[j] - __half2float(h));
    }
    ((uint2*)hi)[i] = H.u;
    ((uint2*)lo)[i] = L.u;
}

// ---------------- weight transpose: fp32 [K][N] -> fp16 [N][K] ----------------
__global__ void wtrans_kernel(const float* __restrict__ W,
                              __half* __restrict__ Whi, int K, int N)
{
    __shared__ float tile[32][33];
    const int n0 = blockIdx.x * 32, k0 = blockIdx.y * 32;
    const int tx = threadIdx.x & 31, ty = threadIdx.x >> 5;
#pragma unroll
    for (int i = 0; i < 32; i += 8)
        tile[ty + i][tx] = W[(size_t)(k0 + ty + i) * N + n0 + tx];
    __syncthreads();
#pragma unroll
    for (int i = 0; i < 32; i += 8)
        Whi[(size_t)(n0 + ty + i) * K + k0 + tx] = __float2half_rn(tile[tx][ty + i]);
}

__global__ void wtrans2_kernel(const float* __restrict__ W,
                               __half* __restrict__ Whi,
                               __half* __restrict__ Wlo, int K, int N)
{
    __shared__ float tile[32][33];
    const int n0 = blockIdx.x * 32, k0 = blockIdx.y * 32;
    const int tx = threadIdx.x & 31, ty = threadIdx.x >> 5;
#pragma unroll
    for (int i = 0; i < 32; i += 8)
        tile[ty + i][tx] = W[(size_t)(k0 + ty + i) * N + n0 + tx];
    __syncthreads();
#pragma unroll
    for (int i = 0; i < 32; i += 8) {
        const float v = tile[tx][ty + i];
        const __half h = __float2half_rn(v);
        const size_t o = (size_t)(n0 + ty + i) * K + k0 + tx;
        Whi[o] = h;
        Wlo[o] = __float2half_rn(v - __half2float(h));
    }
}

// ---------------- zero accumulators (g_out + g_qg) ----------------
__global__ void zero_acc_kernel()
{
    const int i = blockIdx.x * 256 + threadIdx.x;
    if (i < B_ * NH_ * HD_ * HD_) g_out[i] = 0.f;
    if (i < B_ * HID_)            g_qg[i]  = 0.f;
}

__global__ void qg_partial_kernel()  // grid (HID_/256, S_/256, B_)
{
    const int col = blockIdx.x * 256 + threadIdx.x;
    const int b   = blockIdx.z;
    const int r0  = blockIdx.y * 256;
    const float* base = g_q + ((size_t)(b * S_ + r0)) * HID_ + col;
    float s = 0.f;
#pragma unroll 8
    for (int r = 0; r < 256; r++) s += base[(size_t)r * HID_];
    atomicAdd(&g_qg[b * HID_ + col], s);
}

// ---------------- logits ----------------
__global__ void logits_kernel()      // <<<256,256>>>
{
    const int gt   = blockIdx.x * blockDim.x + threadIdx.x;
    const int warp = gt >> 5;
    const int lane = gt & 31;
    const int chunk = warp & 31;
    const int bh    = warp >> 5;
    const int h = bh & 31, b = bh >> 5;
    const int kv = h >> 2;

    float2 qv = *(const float2*)&g_qg[b * HID_ + h * 64 + lane * 2];
    const float sc = 1.0f / (float)S_;
    qv.x *= sc; qv.y *= sc;

    const float* kb = g_k + (size_t)b * S_ * KVW_ + kv * 64 + lane * 2;
    float* lb = g_log + (size_t)bh * S_;
    const int s0 = chunk * 128;
    for (int s = s0; s < s0 + 128; s++) {
        const float2 k2 = *(const float2*)(kb + (size_t)s * KVW_);
        float d = k2.x * qv.x + k2.y * qv.y;
#pragma unroll
        for (int o = 16; o > 0; o >>= 1) d += __shfl_xor_sync(0xffffffffu, d, o);
        if (lane == 0) lb[s] = d;
    }
}

// ---------------- softmax over S per (b,h), scaled by S, in place ----------------
__global__ __launch_bounds__(256)
void softmax_kernel()                // <<<64,256>>>
{
    __shared__ float buf[S_];
    __shared__ float red[256];
    float* row = g_log + (size_t)blockIdx.x * S_;
    const int t = threadIdx.x;

    float m = -1e30f;
    for (int i = t; i < S_; i += 256) { const float v = row[i]; buf[i] = v; m = fmaxf(m, v); }
    red[t] = m; __syncthreads();
    for (int st = 128; st > 0; st >>= 1) { if (t < st) red[t] = fmaxf(red[t], red[t + st]); __syncthreads(); }
    m = red[0]; __syncthreads();

    float sum = 0.f;
    for (int i = t; i < S_; i += 256) { const float e = expf(buf[i] - m); buf[i] = e; sum += e; }
    red[t] = sum; __syncthreads();
    for (int st = 128; st > 0; st >>= 1) { if (t < st) red[t] += red[t + st]; __syncthreads(); }
    const float inv = (float)S_ / red[0];
    for (int i = t; i < S_; i += 256) row[i] = buf[i] * inv;
}

// ---------------- state[b,h] (64x64), split 4 ways over S, atomic merge --------
__global__ __launch_bounds__(256)
void outer_kernel()                  // grid (4, 64)
{
    const int bh = blockIdx.y;
    const int h = bh & 31, b = bh >> 5;
    const int kv = h >> 2;
    __shared__ float ks[32][64];
    __shared__ float vs[32][64];
    const int t = threadIdx.x;
    const int ti = t >> 4, tj = t & 15;
    float acc[4][4] = {};

    const float* kb = g_k + (size_t)b * S_ * KVW_ + kv * 64;
    const float* vb = g_v + (size_t)b * S_ * KVW_ + kv * 64;
    const float* ab = g_log + (size_t)bh * S_;

    const int sBeg = blockIdx.x * (S_ / 4);
    const int sEnd = sBeg + (S_ / 4);
    for (int s0 = sBeg; s0 < sEnd; s0 += 32) {
#pragma unroll
        for (int rep = 0; rep < 2; rep++) {
            const int idx = t + rep * 256;
            const int r = idx >> 4;
            const int c = (idx & 15) << 2;
            const float a = ab[s0 + r];
            const float4 k4 = *(const float4*)(kb + (size_t)(s0 + r) * KVW_ + c);
            *(float4*)&ks[r][c] = make_float4(k4.x * a, k4.y * a, k4.z * a, k4.w * a);
            *(float4*)&vs[r][c] = *(const float4*)(vb + (size_t)(s0 + r) * KVW_ + c);
        }
        __syncthreads();
#pragma unroll
        for (int ss = 0; ss < 32; ss++) {
            float ka[4], vf[4];
            *(float4*)ka = *(const float4*)&ks[ss][ti * 4];
            *(float4*)vf = *(const float4*)&vs[ss][tj * 4];
#pragma unroll
            for (int i = 0; i < 4; i++)
#pragma unroll
                for (int j = 0; j < 4; j++)
                    acc[i][j] = fmaf(ka[i], vf[j], acc[i][j]);
        }
        __syncthreads();
    }
#pragma unroll
    for (int i = 0; i < 4; i++)
#pragma unroll
        for (int j = 0; j < 4; j++)
            atomicAdd(&g_out[(size_t)bh * 4096 + (size_t)(ti * 4 + i) * 64 + tj * 4 + j],
                      acc[i][j]);
}

// ---------------- ctx = phi * (Qk @ state) * CTX_SCALE -> fp16 (hi only) --------
__global__ __launch_bounds__(256)
void ctx_kernel()                    // grid (S_/64, NH_, B_)
{
    const int b = blockIdx.z, h = blockIdx.y, s0 = blockIdx.x * 64;
    __shared__ float Os[64][64];
    __shared__ float Qs[64][68];
    const int t = threadIdx.x;

    const float* ob = g_out + (size_t)(b * NH_ + h) * 4096;
#pragma unroll
    for (int rep = 0; rep < 4; rep++)
        ((float4*)&Os[0][0])[t + rep * 256] = ((const float4*)ob)[t + rep * 256];

    const float* qb = g_q + ((size_t)(b * S_ + s0)) * HID_ + h * 64;
#pragma unroll
    for (int rep = 0; rep < 4; rep++) {
        const int idx = t + rep * 256;
        const int r = idx >> 4;
        const int c = (idx & 15) << 2;
        *(float4*)&Qs[r][c] = *(const float4*)(qb + (size_t)r * HID_ + c);
    }
    __syncthreads();

    const int ti = t >> 4, tj = t & 15;
    float acc[4][4] = {};
#pragma unroll 4
    for (int d = 0; d < 64; d++) {
        float o[4];
        *(float4*)o = *(const float4*)&Os[d][tj * 4];
#pragma unroll
        for (int i = 0; i < 4; i++) {
            const float qv = Qs[ti * 4 + i][d];
#pragma unroll
            for (int j = 0; j < 4; j++)
                acc[i][j] = fmaf(qv, o[j], acc[i][j]);
        }
    }

    const float* pb = g_phi + ((size_t)(b * S_ + s0)) * HID_ + h * 64;
    __half* ph = g_phihi + ((size_t)(b * S_ + s0)) * HID_ + h * 64;
#pragma unroll
    for (int i = 0; i < 4; i++) {
        const size_t off = (size_t)(ti * 4 + i) * HID_ + tj * 4;
        const float4 p = *(const float4*)(pb + off);
        float r[4] = {p.x * acc[i][0] * CTX_SCALE, p.y * acc[i][1] * CTX_SCALE,
                      p.z * acc[i][2] * CTX_SCALE, p.w * acc[i][3] * CTX_SCALE};
        union { __half b[4]; uint2 u; } H;
#pragma unroll
        for (int j = 0; j < 4; j++) H.b[j] = __float2half_rn(r[j]);
        *(uint2*)(ph + off) = H.u;
    }
}

// ---------------- launch ----------------
extern "C" void kernel_launch(void* const* d_in, const int* in_sizes, int n_in,
                              void* d_out, int out_size)
{
    const float* X   = (const float*)d_in[0];
    const float* Wq  = (const float*)d_in[1];
    const float* Wk  = (const float*)d_in[2];
    const float* Wv  = (const float*)d_in[3];
    const float* Wph = (const float*)d_in[4];
    const float* Wo  = (const float*)d_in[5];
    float* out = (float*)d_out;

    float *q, *k, *v, *ph;
    __half *xhi, *xlo, *whi, *wklo, *phihi;
    cudaGetSymbolAddress((void**)&q,     g_q);
    cudaGetSymbolAddress((void**)&k,     g_k);
    cudaGetSymbolAddress((void**)&v,     g_v);
    cudaGetSymbolAddress((void**)&ph,    g_phi);
    cudaGetSymbolAddress((void**)&xhi,   g_xhi);
    cudaGetSymbolAddress((void**)&xlo,   g_xlo);
    cudaGetSymbolAddress((void**)&whi,   g_whi);
    cudaGetSymbolAddress((void**)&wklo,  g_wklo);
    cudaGetSymbolAddress((void**)&phihi, g_phihi);

    cudaFuncSetAttribute(fp16_1pass_gemm,
                         cudaFuncAttributeMaxDynamicSharedMemorySize, SMEM1);
    cudaFuncSetAttribute(fp16split_gemm,
                         cudaFuncAttributeMaxDynamicSharedMemorySize, SMEM2);
    cudaFuncSetAttribute(fp16split3_gemm,
                         cudaFuncAttributeMaxDynamicSharedMemorySize, SMEM3);

    // Conversions
    cvt_split_kernel<<<(ROWS_ * HID_ / 4 + 255) / 256, 256>>>(X, xhi, xlo, ROWS_ * HID_ / 4);
    wtrans_kernel <<<dim3(HID_ / 32, HID_ / 32), 256>>>(Wq,  whi + WQOFF, HID_, HID_);
    wtrans2_kernel<<<dim3(KVW_ / 32, HID_ / 32), 256>>>(Wk,  whi + WKOFF, wklo, HID_, KVW_);
    wtrans_kernel <<<dim3(KVW_ / 32, HID_ / 32), 256>>>(Wv,  whi + WVOFF, HID_, KVW_);
    wtrans_kernel <<<dim3(HID_ / 32, HID_ / 32), 256>>>(Wph, whi + WPOFF, HID_, HID_);

    // Projections. RoPE+kappa fused into Q/K epilogues.
    // Q: 2-pass (feeds softmax via Qg + ctx). K: 3-pass (softmax-critical).
    // V: 2-pass. phi: 1-pass (multiplicative path; X-quant error acceptable).
    fp16split_gemm<<<dim3(HID_ / 128, ROWS_ / 128), 256, SMEM2>>>(
        xhi, xlo, whi + WQOFF, q,  ROWS_, HID_, HID_, 1.0f, 1);
    fp16split3_gemm<<<dim3(KVW_ / 128, ROWS_ / 128), 256, SMEM3>>>(
        xhi, xlo, whi + WKOFF, wklo, k, ROWS_, KVW_, HID_, 1);
    fp16split_gemm<<<dim3(KVW_ / 128, ROWS_ / 128), 256, SMEM2>>>(
        xhi, xlo, whi + WVOFF, v,  ROWS_, KVW_, HID_, 1.0f, 0);
    fp16_1pass_gemm<<<dim3(HID_ / 128, ROWS_ / 128), 256, SMEM1>>>(
        xhi, whi + WPOFF, ph, ROWS_, HID_, HID_, 1.0f);

    wtrans_kernel <<<dim3(HID_ / 32, HID_ / 32), 256>>>(Wo,  whi + WOOFF, HID_, HID_);

    // Zero accumulators, then Qg column sums (1/S folded into logits)
    zero_acc_kernel<<<(B_ * NH_ * HD_ * HD_ + 255) / 256, 256>>>();
    qg_partial_kernel<<<dim3(HID_ / 256, S_ / 256, B_), 256>>>();

    // logits -> alpha -> state
    logits_kernel<<<256, 256>>>();
    softmax_kernel<<<B_ * NH_, 256>>>();
    outer_kernel<<<dim3(4, B_ * NH_), 256>>>();

    // ctx = phi*(Qk@state)*2^-10 -> fp16 hi, then 1-pass Wo GEMM rescales by 2^10
    ctx_kernel<<<dim3(S_ / 64, NH_, B_), 256>>>();
    fp16_1pass_gemm<<<dim3(HID_ / 128, ROWS_ / 128), 256, SMEM1>>>(
        phihi, whi + WOOFF, out, ROWS_, HID_, HID_, CTX_UNSCALE);
}

// round 16
// speedup vs baseline: 2.4902x; 1.1622x over previous
#include <cuda_runtime.h>
#include <cuda_fp16.h>
#include <math.h>
#include <stdint.h>

#define B_    2
#define S_    4096
#define HID_  2048
#define NH_   32
#define NKV_  8
#define HD_   64
#define ROWS_ (B_ * S_)          /* 8192 */
#define KVW_  (NKV_ * HD_)       /* 512  */

#define CTX_SCALE   (1.0f / 1024.0f)
#define CTX_UNSCALE 1024.0f

// weight offsets in the combined transposed-weight buffer (elements)
#define WQOFF 0
#define WKOFF (2048 * 2048)
#define WVOFF (WKOFF + 512 * 2048)
#define WPOFF (WVOFF + 512 * 2048)
#define WOOFF (WPOFF + 2048 * 2048)
#define WTOT  (WOOFF + 2048 * 2048)   /* 7168 * 2048 */

// ---------------- device scratch (no allocs allowed) ----------------
__device__ float g_q  [(size_t)ROWS_ * HID_];
__device__ float g_k  [(size_t)ROWS_ * KVW_];
__device__ float g_v  [(size_t)ROWS_ * KVW_];
__device__ float g_phi[(size_t)ROWS_ * HID_];
__device__ float g_qg [B_ * HID_];
__device__ float g_log[B_ * NH_ * S_];
__device__ float g_out[B_ * NH_ * HD_ * HD_];

__device__ __half g_xhi [(size_t)ROWS_ * HID_];
__device__ __half g_xlo [(size_t)ROWS_ * HID_];     // used by K 3-pass only
__device__ __half g_whi [(size_t)WTOT];
__device__ __half g_wklo[(size_t)KVW_ * HID_];      // lo part for Wk only
__device__ __half g_phihi[(size_t)ROWS_ * HID_];

// ================= fp16 tensor-core GEMM =================
// 1-pass: C = Ahi @ Bhi^T * outScale            (fp16 A and B; Q/V/phi/Wo)
// 3-pass: C = (Ahi+Alo) @ (Bhi+Blo)^T           (exact A, ~fp32 B; K only)
// ropeFlag: apply RoPE+kappa in-register in the epilogue (Q/K projections).
// Block 128x128, BK=32, 8 warps (warp tile 32x64), 3-stage cp.async pipeline
// (2-stage for the 3-pass K path).

#define GPAD 40                 // smem row stride in fp16 elems (conflict-free)
#define SEC  (128 * GPAD)       // 5120 elems per component tile
#define STAGE1 (2 * SEC)        // Ahi, Bhi
#define SMEM1  (3 * STAGE1 * 2) /* 61440: 3 stages */
#define STAGE3 (4 * SEC)        // Ahi, Alo, Bhi, Blo
#define SMEM3  (2 * STAGE3 * 2) /* 81920: 2 stages */

__device__ __forceinline__ void cpasync16(unsigned smaddr, const void* g) {
    asm volatile("cp.async.cg.shared.global [%0], [%1], 16;" :: "r"(smaddr), "l"(g));
}

__device__ __forceinline__ unsigned smaddr_of(const void* p) {
    return (unsigned)__cvta_generic_to_shared(p);
}

#define MMA_FP16(c, a, b0, b1)                                              \
    asm volatile("mma.sync.aligned.m16n8k16.row.col.f32.f16.f16.f32 "       \
                 "{%0,%1,%2,%3}, {%4,%5,%6,%7}, {%8,%9}, {%0,%1,%2,%3};"    \
                 : "+f"(c[0]), "+f"(c[1]), "+f"(c[2]), "+f"(c[3])           \
                 : "r"(a[0]), "r"(a[1]), "r"(a[2]), "r"(a[3]),              \
                   "r"(b0), "r"(b1))

// In-register RoPE + kappa on the 2x8x4 accumulator tile. tg/g/wm as in GEMM.
#define ROPE_KAPPA_EPI(acc, yb, wm, g, tg)                                   \
    do {                                                                     \
        float inv_[8];                                                       \
        _Pragma("unroll")                                                    \
        for (int nt = 0; nt < 4; nt++)                                       \
            _Pragma("unroll")                                                \
            for (int j = 0; j < 2; j++)                                      \
                inv_[nt * 2 + j] =                                           \
                    expf((float)(nt * 8 + (tg) * 2 + j) * -0.28782313662425573f); \
        _Pragma("unroll")                                                    \
        for (int mt = 0; mt < 2; mt++)                                       \
            _Pragma("unroll")                                                \
            for (int rr = 0; rr < 2; rr++) {                                 \
                const int s_ = ((yb) + (wm) + mt * 16 + (g) + rr * 8) & (S_ - 1); \
                _Pragma("unroll")                                            \
                for (int nt = 0; nt < 4; nt++)                               \
                    _Pragma("unroll")                                        \
                    for (int j = 0; j < 2; j++) {                            \
                        float sn_, cs_;                                      \
                        sincosf((float)s_ * inv_[nt * 2 + j], &sn_, &cs_);   \
                        const int jj = rr * 2 + j;                           \
                        const float x1 = acc[mt][nt][jj];                    \
                        const float x2 = acc[mt][nt + 4][jj];                \
                        const float y1 = x1 * cs_ - x2 * sn_;                \
                        const float y2 = x2 * cs_ + x1 * sn_;                \
                        acc[mt][nt][jj]     = (y1 > 0.f) ? (y1 + 1.f) : expf(y1); \
                        acc[mt][nt + 4][jj] = (y2 > 0.f) ? (y2 + 1.f) : expf(y2); \
                    }                                                        \
            }                                                                \
    } while (0)

// ---------------- 1-pass GEMM (Q, V, phi, Wo) ----------------
__device__ __forceinline__ void stage_load1(
    const __half* Ahi, const __half* Bhi,
    __half* sm, int tid, int K, int t)
{
#pragma unroll
    for (int i = 0; i < 2; i++) {
        const int idx = tid + i * 256;
        const int r   = idx >> 2;
        const int c8  = (idx & 3) * 8;
        const size_t goff = (size_t)r * K + (size_t)t * 32 + c8;
        const int soff = r * GPAD + c8;
        cpasync16(smaddr_of(sm + soff),       Ahi + goff);
        cpasync16(smaddr_of(sm + SEC + soff), Bhi + goff);
    }
}

__global__ __launch_bounds__(256)
void fp16_1pass_gemm(const __half* __restrict__ Ahi, const __half* __restrict__ Bhi,
                     float* __restrict__ C, int M, int N, int K, float outScale,
                     int ropeFlag)
{
    extern __shared__ __half smem[];

    const int tid  = threadIdx.x;
    const int wid  = tid >> 5;
    const int lane = tid & 31;
    const int g    = lane >> 2;
    const int tg   = lane & 3;
    const int wm   = (wid >> 1) * 32;
    const int wn   = (wid & 1) * 64;

    const __half* A0 = Ahi + (size_t)(blockIdx.y * 128) * K;
    const __half* B0 = Bhi + (size_t)(blockIdx.x * 128) * K;

    float acc[2][8][4];
#pragma unroll
    for (int mt = 0; mt < 2; mt++)
#pragma unroll
        for (int nt = 0; nt < 8; nt++)
#pragma unroll
            for (int j = 0; j < 4; j++) acc[mt][nt][j] = 0.f;

    const int nT = K >> 5;

    stage_load1(A0, B0, smem, tid, K, 0);
    asm volatile("cp.async.commit_group;");
    stage_load1(A0, B0, smem + STAGE1, tid, K, 1);
    asm volatile("cp.async.commit_group;");

    int cur = 0;
    for (int t = 0; t < nT; t++) {
        if (t + 1 < nT) {
            asm volatile("cp.async.wait_group 1;");
        } else {
            asm volatile("cp.async.wait_group 0;");
        }
        __syncthreads();

        const uint32_t* sA0 = (const uint32_t*)(smem + cur * STAGE1);
        const uint32_t* sB0 = sA0 + SEC / 2;

#pragma unroll
        for (int ks = 0; ks < 2; ks++) {
            uint32_t aH[2][4];
#pragma unroll
            for (int mt = 0; mt < 2; mt++) {
                const int r0 = (wm + mt * 16 + g) * 20 + ks * 8 + tg;
                const int r1 = r0 + 8 * 20;
                aH[mt][0] = sA0[r0];     aH[mt][1] = sA0[r1];
                aH[mt][2] = sA0[r0 + 4]; aH[mt][3] = sA0[r1 + 4];
            }
#pragma unroll
            for (int nt = 0; nt < 8; nt++) {
                const int nb = (wn + nt * 8 + g) * 20 + ks * 8 + tg;
                const uint32_t bH0 = sB0[nb], bH1 = sB0[nb + 4];
#pragma unroll
                for (int mt = 0; mt < 2; mt++)
                    MMA_FP16(acc[mt][nt], aH[mt], bH0, bH1);
            }
        }

        if (t + 2 < nT) {
            const int nxt = (cur + 2 >= 3) ? cur - 1 : cur + 2;
            stage_load1(A0, B0, smem + nxt * STAGE1, tid, K, t + 2);
            asm volatile("cp.async.commit_group;");
        }
        cur = (cur == 2) ? 0 : cur + 1;
    }

    if (ropeFlag) {
        const int yb = blockIdx.y * 128;
        ROPE_KAPPA_EPI(acc, yb, wm, g, tg);
    }

    float* Cb = C + (size_t)(blockIdx.y * 128 + wm) * N + blockIdx.x * 128 + wn;
#pragma unroll
    for (int mt = 0; mt < 2; mt++)
#pragma unroll
        for (int nt = 0; nt < 8; nt++) {
            const int col = nt * 8 + tg * 2;
            *(float2*)&Cb[(size_t)(mt * 16 + g) * N + col] = make_float2(
                acc[mt][nt][0] * outScale, acc[mt][nt][1] * outScale);
            *(float2*)&Cb[(size_t)(mt * 16 + g + 8) * N + col] = make_float2(
                acc[mt][nt][2] * outScale, acc[mt][nt][3] * outScale);
        }
}

// ---- 3-pass variant (A and B split hi/lo) — used for the K projection ----
__device__ __forceinline__ void stage_load3(
    const __half* Ahi, const __half* Alo, const __half* Bhi, const __half* Blo,
    __half* sm, int tid, int K, int t)
{
#pragma unroll
    for (int i = 0; i < 2; i++) {
        const int idx = tid + i * 256;
        const int r   = idx >> 2;
        const int c8  = (idx & 3) * 8;
        const size_t goff = (size_t)r * K + (size_t)t * 32 + c8;
        const int soff = r * GPAD + c8;
        cpasync16(smaddr_of(sm + soff),           Ahi + goff);
        cpasync16(smaddr_of(sm + SEC + soff),     Alo + goff);
        cpasync16(smaddr_of(sm + 2 * SEC + soff), Bhi + goff);
        cpasync16(smaddr_of(sm + 3 * SEC + soff), Blo + goff);
    }
}

__global__ __launch_bounds__(256)
void fp16split3_gemm(const __half* __restrict__ Ahi, const __half* __restrict__ Alo,
                     const __half* __restrict__ Bhi, const __half* __restrict__ Blo,
                     float* __restrict__ C, int M, int N, int K, int ropeFlag)
{
    extern __shared__ __half smem[];

    const int tid  = threadIdx.x;
    const int wid  = tid >> 5;
    const int lane = tid & 31;
    const int g    = lane >> 2;
    const int tg   = lane & 3;
    const int wm   = (wid >> 1) * 32;
    const int wn   = (wid & 1) * 64;

    const __half* A0 = Ahi + (size_t)(blockIdx.y * 128) * K;
    const __half* A1 = Alo + (size_t)(blockIdx.y * 128) * K;
    const __half* B0 = Bhi + (size_t)(blockIdx.x * 128) * K;
    const __half* B1 = Blo + (size_t)(blockIdx.x * 128) * K;

    float acc[2][8][4];
#pragma unroll
    for (int mt = 0; mt < 2; mt++)
#pragma unroll
        for (int nt = 0; nt < 8; nt++)
#pragma unroll
            for (int j = 0; j < 4; j++) acc[mt][nt][j] = 0.f;

    stage_load3(A0, A1, B0, B1, smem, tid, K, 0);
    asm volatile("cp.async.commit_group;");

    const int nT = K >> 5;
    for (int t = 0; t < nT; t++) {
        if (t + 1 < nT) {
            stage_load3(A0, A1, B0, B1, smem + ((t + 1) & 1) * STAGE3, tid, K, t + 1);
            asm volatile("cp.async.commit_group;");
            asm volatile("cp.async.wait_group 1;");
        } else {
            asm volatile("cp.async.wait_group 0;");
        }
        __syncthreads();

        const uint32_t* sA0 = (const uint32_t*)(smem + (t & 1) * STAGE3);
        const uint32_t* sA1 = sA0 + SEC / 2;
        const uint32_t* sB0 = sA0 + SEC;
        const uint32_t* sB1 = sA0 + 3 * (SEC / 2);

#pragma unroll
        for (int ks = 0; ks < 2; ks++) {
            uint32_t aH[2][4], aL[2][4];
#pragma unroll
            for (int mt = 0; mt < 2; mt++) {
                const int r0 = (wm + mt * 16 + g) * 20 + ks * 8 + tg;
                const int r1 = r0 + 8 * 20;
                aH[mt][0] = sA0[r0];     aH[mt][1] = sA0[r1];
                aH[mt][2] = sA0[r0 + 4]; aH[mt][3] = sA0[r1 + 4];
                aL[mt][0] = sA1[r0];     aL[mt][1] = sA1[r1];
                aL[mt][2] = sA1[r0 + 4]; aL[mt][3] = sA1[r1 + 4];
            }
#pragma unroll
            for (int nt = 0; nt < 8; nt++) {
                const int nb = (wn + nt * 8 + g) * 20 + ks * 8 + tg;
                const uint32_t bH0 = sB0[nb], bH1 = sB0[nb + 4];
                const uint32_t bL0 = sB1[nb], bL1 = sB1[nb + 4];
#pragma unroll
                for (int mt = 0; mt < 2; mt++) {
                    MMA_FP16(acc[mt][nt], aH[mt], bH0, bH1);
                    MMA_FP16(acc[mt][nt], aH[mt], bL0, bL1);
                    MMA_FP16(acc[mt][nt], aL[mt], bH0, bH1);
                }
            }
        }
        __syncthreads();
    }

    if (ropeFlag) {
        const int yb = blockIdx.y * 128;
        ROPE_KAPPA_EPI(acc, yb, wm, g, tg);
    }

    float* Cb = C + (size_t)(blockIdx.y * 128 + wm) * N + blockIdx.x * 128 + wn;
#pragma unroll
    for (int mt = 0; mt < 2; mt++)
#pragma unroll
        for (int nt = 0; nt < 8; nt++) {
            const int col = nt * 8 + tg * 2;
            *(float2*)&Cb[(size_t)(mt * 16 + g) * N + col] =
                make_float2(acc[mt][nt][0], acc[mt][nt][1]);
            *(float2*)&Cb[(size_t)(mt * 16 + g + 8) * N + col] =
                make_float2(acc[mt][nt][2], acc[mt][nt][3]);
        }
}

// ---------------- fp32 -> (hi, lo) fp16 split ----------------
__global__ void cvt_split_kernel(const float* __restrict__ in,
                                 __half* __restrict__ hi,
                                 __half* __restrict__ lo, int n4)
{
    const int i = blockIdx.x * 256 + threadIdx.x;
    if (i >= n4) return;
    const float4 x = ((const float4*)in)[i];
    union { __half b[4]; uint2 u; } H, L;
    float v[4] = {x.x, x.y, x.z, x.w};
#pragma unroll
    for (int j = 0; j < 4; j++) {
        const __half h = __float2half_rn(v[j]);
        H.b[j] = h;
        L.b[j] = __float2half_rn(v[j] - __half2float(h));
    }
    ((uint2*)hi)[i] = H.u;
    ((uint2*)lo)[i] = L.u;
}

// ---------------- weight transpose: fp32 [K][N] -> fp16 [N][K] ----------------
__global__ void wtrans_kernel(const float* __restrict__ W,
                              __half* __restrict__ Whi, int K, int N)
{
    __shared__ float tile[32][33];
    const int n0 = blockIdx.x * 32, k0 = blockIdx.y * 32;
    const int tx = threadIdx.x & 31, ty = threadIdx.x >> 5;
#pragma unroll
    for (int i = 0; i < 32; i += 8)
        tile[ty + i][tx] = W[(size_t)(k0 + ty + i) * N + n0 + tx];
    __syncthreads();
#pragma unroll
    for (int i = 0; i < 32; i += 8)
        Whi[(size_t)(n0 + ty + i) * K + k0 + tx] = __float2half_rn(tile[tx][ty + i]);
}

__global__ void wtrans2_kernel(const float* __restrict__ W,
                               __half* __restrict__ Whi,
                               __half* __restrict__ Wlo, int K, int N)
{
    __shared__ float tile[32][33];
    const int n0 = blockIdx.x * 32, k0 = blockIdx.y * 32;
    const int tx = threadIdx.x & 31, ty = threadIdx.x >> 5;
#pragma unroll
    for (int i = 0; i < 32; i += 8)
        tile[ty + i][tx] = W[(size_t)(k0 + ty + i) * N + n0 + tx];
    __syncthreads();
#pragma unroll
    for (int i = 0; i < 32; i += 8) {
        const float v = tile[tx][ty + i];
        const __half h = __float2half_rn(v);
        const size_t o = (size_t)(n0 + ty + i) * K + k0 + tx;
        Whi[o] = h;
        Wlo[o] = __float2half_rn(v - __half2float(h));
    }
}

// ---------------- zero accumulators (g_out + g_qg) ----------------
__global__ void zero_acc_kernel()
{
    const int i = blockIdx.x * 256 + threadIdx.x;
    if (i < B_ * NH_ * HD_ * HD_) g_out[i] = 0.f;
    if (i < B_ * HID_)            g_qg[i]  = 0.f;
}

__global__ void qg_partial_kernel()  // grid (HID_/256, S_/256, B_)
{
    const int col = blockIdx.x * 256 + threadIdx.x;
    const int b   = blockIdx.z;
    const int r0  = blockIdx.y * 256;
    const float* base = g_q + ((size_t)(b * S_ + r0)) * HID_ + col;
    float s = 0.f;
#pragma unroll 8
    for (int r = 0; r < 256; r++) s += base[(size_t)r * HID_];
    atomicAdd(&g_qg[b * HID_ + col], s);
}

// ---------------- logits ----------------
__global__ void logits_kernel()      // <<<256,256>>>
{
    const int gt   = blockIdx.x * blockDim.x + threadIdx.x;
    const int warp = gt >> 5;
    const int lane = gt & 31;
    const int chunk = warp & 31;
    const int bh    = warp >> 5;
    const int h = bh & 31, b = bh >> 5;
    const int kv = h >> 2;

    float2 qv = *(const float2*)&g_qg[b * HID_ + h * 64 + lane * 2];
    const float sc = 1.0f / (float)S_;
    qv.x *= sc; qv.y *= sc;

    const float* kb = g_k + (size_t)b * S_ * KVW_ + kv * 64 + lane * 2;
    float* lb = g_log + (size_t)bh * S_;
    const int s0 = chunk * 128;
    for (int s = s0; s < s0 + 128; s++) {
        const float2 k2 = *(const float2*)(kb + (size_t)s * KVW_);
        float d = k2.x * qv.x + k2.y * qv.y;
#pragma unroll
        for (int o = 16; o > 0; o >>= 1) d += __shfl_xor_sync(0xffffffffu, d, o);
        if (lane == 0) lb[s] = d;
    }
}

// ---------------- softmax over S per (b,h), scaled by S, in place ----------------
__global__ __launch_bounds__(256)
void softmax_kernel()                // <<<64,256>>>
{
    __shared__ float buf[S_];
    __shared__ float red[256];
    float* row = g_log + (size_t)blockIdx.x * S_;
    const int t = threadIdx.x;

    float m = -1e30f;
    for (int i = t; i < S_; i += 256) { const float v = row[i]; buf[i] = v; m = fmaxf(m, v); }
    red[t] = m; __syncthreads();
    for (int st = 128; st > 0; st >>= 1) { if (t < st) red[t] = fmaxf(red[t], red[t + st]); __syncthreads(); }
    m = red[0]; __syncthreads();

    float sum = 0.f;
    for (int i = t; i < S_; i += 256) { const float e = expf(buf[i] - m); buf[i] = e; sum += e; }
    red[t] = sum; __syncthreads();
    for (int st = 128; st > 0; st >>= 1) { if (t < st) red[t] += red[t + st]; __syncthreads(); }
    const float inv = (float)S_ / red[0];
    for (int i = t; i < S_; i += 256) row[i] = buf[i] * inv;
}

// ---------------- state[b,h] (64x64), split 4 ways over S, atomic merge --------
__global__ __launch_bounds__(256)
void outer_kernel()                  // grid (4, 64)
{
    const int bh = blockIdx.y;
    const int h = bh & 31, b = bh >> 5;
    const int kv = h >> 2;
    __shared__ float ks[32][64];
    __shared__ float vs[32][64];
    const int t = threadIdx.x;
    const int ti = t >> 4, tj = t & 15;
    float acc[4][4] = {};

    const float* kb = g_k + (size_t)b * S_ * KVW_ + kv * 64;
    const float* vb = g_v + (size_t)b * S_ * KVW_ + kv * 64;
    const float* ab = g_log + (size_t)bh * S_;

    const int sBeg = blockIdx.x * (S_ / 4);
    const int sEnd = sBeg + (S_ / 4);
    for (int s0 = sBeg; s0 < sEnd; s0 += 32) {
#pragma unroll
        for (int rep = 0; rep < 2; rep++) {
            const int idx = t + rep * 256;
            const int r = idx >> 4;
            const int c = (idx & 15) << 2;
            const float a = ab[s0 + r];
            const float4 k4 = *(const float4*)(kb + (size_t)(s0 + r) * KVW_ + c);
            *(float4*)&ks[r][c] = make_float4(k4.x * a, k4.y * a, k4.z * a, k4.w * a);
            *(float4*)&vs[r][c] = *(const float4*)(vb + (size_t)(s0 + r) * KVW_ + c);
        }
        __syncthreads();
#pragma unroll
        for (int ss = 0; ss < 32; ss++) {
            float ka[4], vf[4];
            *(float4*)ka = *(const float4*)&ks[ss][ti * 4];
            *(float4*)vf = *(const float4*)&vs[ss][tj * 4];
#pragma unroll
            for (int i = 0; i < 4; i++)
#pragma unroll
                for (int j = 0; j < 4; j++)
                    acc[i][j] = fmaf(ka[i], vf[j], acc[i][j]);
        }
        __syncthreads();
    }
#pragma unroll
    for (int i = 0; i < 4; i++)
#pragma unroll
        for (int j = 0; j < 4; j++)
            atomicAdd(&g_out[(size_t)bh * 4096 + (size_t)(ti * 4 + i) * 64 + tj * 4 + j],
                      acc[i][j]);
}

// ---------------- ctx = phi * (Qk @ state) * CTX_SCALE -> fp16 (hi only) --------
__global__ __launch_bounds__(256)
void ctx_kernel()                    // grid (S_/64, NH_, B_)
{
    const int b = blockIdx.z, h = blockIdx.y, s0 = blockIdx.x * 64;
    __shared__ float Os[64][64];
    __shared__ float Qs[64][68];
    const int t = threadIdx.x;

    const float* ob = g_out + (size_t)(b * NH_ + h) * 4096;
#pragma unroll
    for (int rep = 0; rep < 4; rep++)
        ((float4*)&Os[0][0])[t + rep * 256] = ((const float4*)ob)[t + rep * 256];

    const float* qb = g_q + ((size_t)(b * S_ + s0)) * HID_ + h * 64;
#pragma unroll
    for (int rep = 0; rep < 4; rep++) {
        const int idx = t + rep * 256;
        const int r = idx >> 4;
        const int c = (idx & 15) << 2;
        *(float4*)&Qs[r][c] = *(const float4*)(qb + (size_t)r * HID_ + c);
    }
    __syncthreads();

    const int ti = t >> 4, tj = t & 15;
    float acc[4][4] = {};
#pragma unroll 4
    for (int d = 0; d < 64; d++) {
        float o[4];
        *(float4*)o = *(const float4*)&Os[d][tj * 4];
#pragma unroll
        for (int i = 0; i < 4; i++) {
            const float qv = Qs[ti * 4 + i][d];
#pragma unroll
            for (int j = 0; j < 4; j++)
                acc[i][j] = fmaf(qv, o[j], acc[i][j]);
        }
    }

    const float* pb = g_phi + ((size_t)(b * S_ + s0)) * HID_ + h * 64;
    __half* ph = g_phihi + ((size_t)(b * S_ + s0)) * HID_ + h * 64;
#pragma unroll
    for (int i = 0; i < 4; i++) {
        const size_t off = (size_t)(ti * 4 + i) * HID_ + tj * 4;
        const float4 p = *(const float4*)(pb + off);
        float r[4] = {p.x * acc[i][0] * CTX_SCALE, p.y * acc[i][1] * CTX_SCALE,
                      p.z * acc[i][2] * CTX_SCALE, p.w * acc[i][3] * CTX_SCALE};
        union { __half b[4]; uint2 u; } H;
#pragma unroll
        for (int j = 0; j < 4; j++) H.b[j] = __float2half_rn(r[j]);
        *(uint2*)(ph + off) = H.u;
    }
}

// ---------------- launch ----------------
extern "C" void kernel_launch(void* const* d_in, const int* in_sizes, int n_in,
                              void* d_out, int out_size)
{
    const float* X   = (const float*)d_in[0];
    const float* Wq  = (const float*)d_in[1];
    const float* Wk  = (const float*)d_in[2];
    const float* Wv  = (const float*)d_in[3];
    const float* Wph = (const float*)d_in[4];
    const float* Wo  = (const float*)d_in[5];
    float* out = (float*)d_out;

    float *q, *k, *v, *ph;
    __half *xhi, *xlo, *whi, *wklo, *phihi;
    cudaGetSymbolAddress((void**)&q,     g_q);
    cudaGetSymbolAddress((void**)&k,     g_k);
    cudaGetSymbolAddress((void**)&v,     g_v);
    cudaGetSymbolAddress((void**)&ph,    g_phi);
    cudaGetSymbolAddress((void**)&xhi,   g_xhi);
    cudaGetSymbolAddress((void**)&xlo,   g_xlo);
    cudaGetSymbolAddress((void**)&whi,   g_whi);
    cudaGetSymbolAddress((void**)&wklo,  g_wklo);
    cudaGetSymbolAddress((void**)&phihi, g_phihi);

    cudaFuncSetAttribute(fp16_1pass_gemm,
                         cudaFuncAttributeMaxDynamicSharedMemorySize, SMEM1);
    cudaFuncSetAttribute(fp16split3_gemm,
                         cudaFuncAttributeMaxDynamicSharedMemorySize, SMEM3);

    // Conversions (xlo only feeds the K 3-pass GEMM)
    cvt_split_kernel<<<(ROWS_ * HID_ / 4 + 255) / 256, 256>>>(X, xhi, xlo, ROWS_ * HID_ / 4);
    wtrans_kernel <<<dim3(HID_ / 32, HID_ / 32), 256>>>(Wq,  whi + WQOFF, HID_, HID_);
    wtrans2_kernel<<<dim3(KVW_ / 32, HID_ / 32), 256>>>(Wk,  whi + WKOFF, wklo, HID_, KVW_);
    wtrans_kernel <<<dim3(KVW_ / 32, HID_ / 32), 256>>>(Wv,  whi + WVOFF, HID_, KVW_);
    wtrans_kernel <<<dim3(HID_ / 32, HID_ / 32), 256>>>(Wph, whi + WPOFF, HID_, HID_);

    // Projections. RoPE+kappa fused into Q/K epilogues.
    // K: 3-pass (softmax-critical). Q/V/phi: 1-pass (error budget audited).
    fp16_1pass_gemm<<<dim3(HID_ / 128, ROWS_ / 128), 256, SMEM1>>>(
        xhi, whi + WQOFF, q,  ROWS_, HID_, HID_, 1.0f, 1);
    fp16split3_gemm<<<dim3(KVW_ / 128, ROWS_ / 128), 256, SMEM3>>>(
        xhi, xlo, whi + WKOFF, wklo, k, ROWS_, KVW_, HID_, 1);
    fp16_1pass_gemm<<<dim3(KVW_ / 128, ROWS_ / 128), 256, SMEM1>>>(
        xhi, whi + WVOFF, v,  ROWS_, KVW_, HID_, 1.0f, 0);
    fp16_1pass_gemm<<<dim3(HID_ / 128, ROWS_ / 128), 256, SMEM1>>>(
        xhi, whi + WPOFF, ph, ROWS_, HID_, HID_, 1.0f, 0);

    wtrans_kernel <<<dim3(HID_ / 32, HID_ / 32), 256>>>(Wo,  whi + WOOFF, HID_, HID_);

    // Zero accumulators, then Qg column sums (1/S folded into logits)
    zero_acc_kernel<<<(B_ * NH_ * HD_ * HD_ + 255) / 256, 256>>>();
    qg_partial_kernel<<<dim3(HID_ / 256, S_ / 256, B_), 256>>>();

    // logits -> alpha -> state
    logits_kernel<<<256, 256>>>();
    softmax_kernel<<<B_ * NH_, 256>>>();
    outer_kernel<<<dim3(4, B_ * NH_), 256>>>();

    // ctx = phi*(Qk@state)*2^-10 -> fp16 hi, then 1-pass Wo GEMM rescales by 2^10
    ctx_kernel<<<dim3(S_ / 64, NH_, B_), 256>>>();
    fp16_1pass_gemm<<<dim3(HID_ / 128, ROWS_ / 128), 256, SMEM1>>>(
        phihi, whi + WOOFF, out, ROWS_, HID_, HID_, CTX_UNSCALE, 0);
}